// round 8
// baseline (speedup 1.0000x reference)
#include <cuda_runtime.h>
#include <math.h>
#include <mma.h>

using namespace nvcuda;

#define NN 4096
#define FIN 3000
#define FOUT 64
#define MAXNNZ 512
#define KSPL 4
#define FULLM 0xffffffffu

// ---------------- scratch (static device memory; no allocation) ----------------
__device__ float g_X   [2*NN*FOUT];      // [X1; X1a]
__device__ float g_Wh  [2*NN*FOUT];
__device__ float g_s   [2*NN];
__device__ float g_d   [2*NN];
__device__ float g_att [2*NN*FOUT];
__device__ float g_t1  [2*NN*256];
__device__ float g_t2  [2*NN*128];
__device__ float g_adjz[NN*FOUT];
__device__ float g_dcat[4*NN*FOUT];      // [gv; gva; emb; emba]
__device__ float g_dh  [4*NN*128];
__device__ float g_qcat[4*NN*FOUT];      // [dc; dca; dpl; dmi]
__device__ float g_u   [2*NN*FOUT];      // [u; ua]
__device__ float g_part[2*KSPL*NN*FOUT];
__device__ float g_WT  [FOUT*FOUT];
__device__ int   g_adj_idx[NN*MAXNNZ];
__device__ int   g_adj_cnt[NN];
__device__ int   g_gn_idx [NN*MAXNNZ];
__device__ int   g_gn_cnt [NN];

// precomputed tf32 hi/lo weight buffers (concatenated)
#define OFF_W1   0
#define OFF_W2   192000
#define OFF_ATTW 384000
#define OFF_MW1  388096
#define OFF_MW2  404480
#define OFF_MW3  437248
#define OFF_DW1  445440
#define OFF_DW2  453632
#define OFF_WT   461824
#define SPLIT_TOTAL 465920
__device__ float g_Bhi[SPLIT_TOTAL];
__device__ float g_Blo[SPLIT_TOTAL];

__device__ __forceinline__ float t32(float x) { return wmma::__float_to_tf32(x); }

// ---------------- weight hi/lo split (one launch, 9 segments) -----------------
struct SplitArgs {
    const float* src[9];
    int n[9];
    int off[9];
};
__global__ void split_kernel(SplitArgs a, float* __restrict__ hi, float* __restrict__ lo) {
    int seg = blockIdx.y;
    int i = blockIdx.x * 256 + threadIdx.x;
    if (i < a.n[seg]) {
        float x = a.src[seg][i];
        float h = t32(x);
        hi[a.off[seg] + i] = h;
        lo[a.off[seg] + i] = t32(x - h);
    }
}

// ---------------- build sparse row lists (both matrices, one launch) ----------
__global__ void build_list_kernel(const float* __restrict__ matA, int* __restrict__ idxA,
                                  int* __restrict__ cntA,
                                  const float* __restrict__ matB, int* __restrict__ idxB,
                                  int* __restrict__ cntB) {
    int row = blockIdx.x;
    const float* mat = blockIdx.y ? matB : matA;
    int* idx = blockIdx.y ? idxB : idxA;
    int* cnt = blockIdx.y ? cntB : cntA;
    int tid = threadIdx.x;
    int wid = tid >> 5, lane = tid & 31;
    const float4* r4 = (const float4*)(mat + (size_t)row * NN);
    __shared__ int wsum[8];
    __shared__ int woff[8];
    float v[16];
    #pragma unroll
    for (int q = 0; q < 4; q++) {
        float4 x = r4[tid * 4 + q];
        v[q * 4 + 0] = x.x; v[q * 4 + 1] = x.y; v[q * 4 + 2] = x.z; v[q * 4 + 3] = x.w;
    }
    int base = tid * 16;
    int c = 0;
    #pragma unroll
    for (int j = 0; j < 16; j++) c += (v[j] != 0.0f);
    int inc = c;
    #pragma unroll
    for (int o = 1; o < 32; o <<= 1) {
        int t = __shfl_up_sync(FULLM, inc, o);
        if (lane >= o) inc += t;
    }
    if (lane == 31) wsum[wid] = inc;
    __syncthreads();
    if (tid < 8) {
        int t = wsum[tid];
        int iv = t;
        #pragma unroll
        for (int o = 1; o < 8; o <<= 1) {
            int u = __shfl_up_sync(0xffu, iv, o);
            if (tid >= o) iv += u;
        }
        woff[tid] = iv - t;
        if (tid == 7) cnt[row] = iv;
    }
    __syncthreads();
    int o = woff[wid] + inc - c;
    int* dst = idx + (size_t)row * MAXNNZ;
    #pragma unroll
    for (int j = 0; j < 16; j++) {
        if (v[j] != 0.0f) dst[o++] = base + j;
    }
}

// ---------------- tf32 WMMA GEMM v2: warp owns 32 rows x 64 cols --------------
// C = act(A[M,K] @ B[K,N] + bias). BM = WM*32, BN = 64, threads = WM*32.
// PREC=3: 3xtf32 compensated (B hi/lo precomputed, A split at smem store).
// PREC=1: plain tf32.
// split-K via blockIdx.z: kz = bz % kspl; bz >= kspl uses A2.
// act: 0 none, 1 relu, 2 raw->C + relu->C2, 3 raw->C only rows<NN + relu->C2.
template<int PREC, int WM, int BK>
__global__ __launch_bounds__(WM * 32, 4)
void gemm_tc(const float* __restrict__ A, const float* __restrict__ A2,
             const float* __restrict__ Bhi, const float* __restrict__ Blo,
             const float* __restrict__ bias, float* __restrict__ C,
             float* __restrict__ C2, int M, int N, int K,
             int kChunk, int kspl, long long partStride, int act) {
    constexpr int BM = WM * 32;
    constexpr int TPB = BM;               // one A row per thread
    constexpr int AFR = BK / 4;           // A float4s per thread
    constexpr int BROWS = TPB / 16;       // B k-rows per pass
    constexpr int BITER = BK / BROWS;     // B float4s per thread
    constexpr int LDA = BK + 4;

    int bz = blockIdx.z;
    int kz = bz % kspl;
    const float* Asrc = (bz < kspl) ? A : A2;
    int k0 = kz * kChunk;
    int k1 = min(K, k0 + kChunk);
    float* Cp = C + (long long)bz * partStride;
    int row0 = blockIdx.y * BM;
    int col0 = blockIdx.x * 64;
    int tid = threadIdx.x;
    int wid = tid >> 5;
    int lane = tid & 31;

    __shared__ float Ah[BM][LDA];
    __shared__ float Al[PREC == 3 ? BM : 1][LDA];
    __shared__ float Bh[BK][72];
    __shared__ float Bl[PREC == 3 ? BK : 1][72];
    __shared__ float Cb[WM][256];

    wmma::fragment<wmma::accumulator, 16, 16, 8, float> acc[2][4];
    #pragma unroll
    for (int g = 0; g < 2; g++)
        #pragma unroll
        for (int f = 0; f < 4; f++) wmma::fill_fragment(acc[g][f], 0.0f);

    const float* Arow = Asrc + (size_t)(row0 + tid) * K;
    int bn = (tid & 15) * 4;
    int bkb = tid >> 4;
    int gnB = col0 + bn;

    float4 aR[AFR], bhR[BITER], blR[BITER];
    const float4 f4z = make_float4(0.f, 0.f, 0.f, 0.f);

    auto loadTiles = [&](int kk) {
        #pragma unroll
        for (int v = 0; v < AFR; v++) {
            int gk = kk + v * 4;
            aR[v] = (gk < k1) ? *(const float4*)(Arow + gk) : f4z;
        }
        #pragma unroll
        for (int i = 0; i < BITER; i++) {
            int gkb = kk + bkb + i * BROWS;
            bhR[i] = f4z;
            if (PREC == 3) blR[i] = f4z;
            if (gkb < k1 && gnB < N) {
                bhR[i] = *(const float4*)(Bhi + (size_t)gkb * N + gnB);
                if (PREC == 3) blR[i] = *(const float4*)(Blo + (size_t)gkb * N + gnB);
            }
        }
    };
    auto storeTiles = [&]() {
        #pragma unroll
        for (int v = 0; v < AFR; v++) {
            int c = v * 4;
            float* dh = &Ah[tid][c];
            float* dl = &Al[PREC == 3 ? tid : 0][c];
            float h;
            h = t32(aR[v].x); dh[0] = h; if (PREC == 3) dl[0] = t32(aR[v].x - h);
            h = t32(aR[v].y); dh[1] = h; if (PREC == 3) dl[1] = t32(aR[v].y - h);
            h = t32(aR[v].z); dh[2] = h; if (PREC == 3) dl[2] = t32(aR[v].z - h);
            h = t32(aR[v].w); dh[3] = h; if (PREC == 3) dl[3] = t32(aR[v].w - h);
        }
        #pragma unroll
        for (int i = 0; i < BITER; i++) {
            *(float4*)&Bh[bkb + i * BROWS][bn] = bhR[i];
            if (PREC == 3) *(float4*)&Bl[bkb + i * BROWS][bn] = blR[i];
        }
    };

    loadTiles(k0);
    for (int kk = k0; kk < k1; kk += BK) {
        storeTiles();
        __syncthreads();
        int nk = kk + BK;
        if (nk < k1) loadTiles(nk);   // prefetch; latency hidden by mma below
        #pragma unroll
        for (int ks = 0; ks < BK; ks += 8) {
            wmma::fragment<wmma::matrix_a, 16, 16, 8, wmma::precision::tf32, wmma::row_major> ah[2], al[2];
            wmma::load_matrix_sync(ah[0], &Ah[wid * 32][ks], LDA);
            wmma::load_matrix_sync(ah[1], &Ah[wid * 32 + 16][ks], LDA);
            if (PREC == 3) {
                wmma::load_matrix_sync(al[0], &Al[wid * 32][ks], LDA);
                wmma::load_matrix_sync(al[1], &Al[wid * 32 + 16][ks], LDA);
            }
            #pragma unroll
            for (int f = 0; f < 4; f++) {
                wmma::fragment<wmma::matrix_b, 16, 16, 8, wmma::precision::tf32, wmma::row_major> bh, bl;
                wmma::load_matrix_sync(bh, &Bh[ks][f * 16], 72);
                if (PREC == 3) {
                    wmma::load_matrix_sync(bl, &Bl[ks][f * 16], 72);
                    #pragma unroll
                    for (int g = 0; g < 2; g++) {
                        wmma::mma_sync(acc[g][f], ah[g], bl, acc[g][f]);
                        wmma::mma_sync(acc[g][f], al[g], bh, acc[g][f]);
                    }
                }
                #pragma unroll
                for (int g = 0; g < 2; g++)
                    wmma::mma_sync(acc[g][f], ah[g], bh, acc[g][f]);
            }
        }
        __syncthreads();
    }

    #pragma unroll
    for (int g = 0; g < 2; g++) {
        int r0 = row0 + wid * 32 + g * 16;
        #pragma unroll
        for (int f = 0; f < 4; f++) {
            int c0 = col0 + f * 16;
            __syncwarp();
            wmma::store_matrix_sync(&Cb[wid][0], acc[g][f], 16, wmma::mem_row_major);
            __syncwarp();
            for (int e = lane; e < 256; e += 32) {
                int rr = e >> 4, cc = e & 15;
                int c = c0 + cc;
                if (c < N) {
                    float v = Cb[wid][e];
                    if (bias) v += bias[c];
                    int gr = r0 + rr;
                    size_t oi = (size_t)gr * N + c;
                    if (act == 0) {
                        Cp[oi] = v;
                    } else if (act == 1) {
                        Cp[oi] = fmaxf(v, 0.0f);
                    } else if (act == 2) {
                        Cp[oi] = v;
                        C2[oi] = fmaxf(v, 0.0f);
                    } else {  // act == 3
                        if (gr < NN) Cp[oi] = v;
                        C2[oi] = fmaxf(v, 0.0f);
                    }
                }
            }
        }
    }
}

// fused split-K reduce over both feat GEMMs -> X [2*NN, FOUT]
__global__ void reduce_part_kernel(const float* __restrict__ part, float* __restrict__ out) {
    int i = blockIdx.x * blockDim.x + threadIdx.x;
    const int HALF = NN * FOUT;
    if (i < 2 * HALF) {
        int h = i >= HALF;
        const float* base = part + (size_t)h * KSPL * HALF;
        int j = i - h * HALF;
        float s = 0.0f;
        #pragma unroll
        for (int z = 0; z < KSPL; z++) s += base[(size_t)z * HALF + j];
        out[i] = s;
    }
}

// ---------------- s = Wh@a_src, d = Wh@a_dst (warp per row, 8192 rows) --------
__global__ void sd_kernel(const float* __restrict__ Wh, const float* __restrict__ a_src,
                          const float* __restrict__ a_dst, float* __restrict__ s,
                          float* __restrict__ d) {
    int row = blockIdx.x * 8 + (threadIdx.x >> 5);
    int lane = threadIdx.x & 31;
    if (row < 2 * NN) {
        const float* w = Wh + (size_t)row * 64;
        float vs = w[lane] * a_src[lane] + w[lane + 32] * a_src[lane + 32];
        float vd = w[lane] * a_dst[lane] + w[lane + 32] * a_dst[lane + 32];
        #pragma unroll
        for (int o = 16; o > 0; o >>= 1) {
            vs += __shfl_down_sync(FULLM, vs, o);
            vd += __shfl_down_sync(FULLM, vd, o);
        }
        if (lane == 0) { s[row] = vs; d[row] = vd; }
    }
}

// ---------------- warp-per-row attention (online softmax), 8192 rows ----------
__global__ void att_warp_kernel(const int* __restrict__ idx, const int* __restrict__ cnt,
                                const float* __restrict__ s, const float* __restrict__ d,
                                const float* __restrict__ Wh, float* __restrict__ out) {
    int row = blockIdx.x * 8 + (threadIdx.x >> 5);
    int lane = threadIdx.x & 31;
    if (row >= 2 * NN) return;
    int grow = row & (NN - 1);
    int off = row & NN;
    int n = cnt[grow];
    const int* lst = idx + (size_t)grow * MAXNNZ;
    float si = s[row];
    float m = -3.4e38f, ssum = 0.0f, a0 = 0.0f, a1 = 0.0f;
    for (int base = 0; base < n; base += 32) {
        int t = base + lane;
        int j = 0;
        float e = -3.4e38f;
        if (t < n) {
            j = lst[t];
            float v = si + d[j + off];
            e = v > 0.0f ? v : 0.2f * v;
        }
        float cm = e;
        #pragma unroll
        for (int o = 16; o > 0; o >>= 1) cm = fmaxf(cm, __shfl_xor_sync(FULLM, cm, o));
        float nm = fmaxf(m, cm);
        float scale = expf(m - nm);
        a0 *= scale; a1 *= scale; ssum *= scale;
        float w = (t < n) ? expf(e - nm) : 0.0f;
        float cs = w;
        #pragma unroll
        for (int o = 16; o > 0; o >>= 1) cs += __shfl_xor_sync(FULLM, cs, o);
        ssum += cs;
        int lim = min(32, n - base);
        for (int q = 0; q < lim; q++) {
            float wq = __shfl_sync(FULLM, w, q);
            int jq = __shfl_sync(FULLM, j, q);
            const float* r = Wh + (size_t)(jq + off) * 64;
            a0 += wq * r[lane];
            a1 += wq * r[lane + 32];
        }
        m = nm;
    }
    float inv = 1.0f / ssum;
    out[(size_t)row * 64 + lane] = a0 * inv;
    out[(size_t)row * 64 + lane + 32] = a1 * inv;
}

// ---------------- adjz = adj @ z (warp per row; z lives in d_out) -------------
__global__ void agg_warp_kernel(const int* __restrict__ idx, const int* __restrict__ cnt,
                                const float* __restrict__ z, float* __restrict__ out) {
    int row = blockIdx.x * 8 + (threadIdx.x >> 5);
    int lane = threadIdx.x & 31;
    if (row >= NN) return;
    int n = cnt[row];
    const int* lst = idx + (size_t)row * MAXNNZ;
    float a0 = 0.0f, a1 = 0.0f;
    for (int base = 0; base < n; base += 32) {
        int t = base + lane;
        int j = (t < n) ? lst[t] : 0;
        int lim = min(32, n - base);
        for (int q = 0; q < lim; q++) {
            int jq = __shfl_sync(FULLM, j, q);
            const float* r = z + (size_t)jq * 64;
            a0 += r[lane];
            a1 += r[lane + 32];
        }
    }
    out[(size_t)row * 64 + lane] = a0;
    out[(size_t)row * 64 + lane + 32] = a1;
}

// ---------------- warp-per-row readout: mean, L2-norm, sigmoid (8192 rows) ----
__global__ void readout_warp_kernel(const int* __restrict__ idx, const int* __restrict__ cnt,
                                    float* __restrict__ dcat) {
    int row = blockIdx.x * 8 + (threadIdx.x >> 5);
    int lane = threadIdx.x & 31;
    if (row >= 2 * NN) return;
    int grow = row & (NN - 1);
    int n = cnt[grow];
    const int* lst = idx + (size_t)grow * MAXNNZ;
    int off = (row < NN) ? 2 * NN : 3 * NN;
    float a0 = 0.0f, a1 = 0.0f;
    for (int base = 0; base < n; base += 32) {
        int t = base + lane;
        int j = (t < n) ? lst[t] : 0;
        int lim = min(32, n - base);
        for (int q = 0; q < lim; q++) {
            int jq = __shfl_sync(FULLM, j, q);
            const float* r = dcat + (size_t)(off + jq) * 64;
            a0 += r[lane];
            a1 += r[lane + 32];
        }
    }
    float invn = 1.0f / (float)n;
    float v0 = a0 * invn, v1 = a1 * invn;
    float ss = v0 * v0 + v1 * v1;
    #pragma unroll
    for (int o = 16; o > 0; o >>= 1) ss += __shfl_xor_sync(FULLM, ss, o);
    float den = fmaxf(sqrtf(ss), 1e-12f);
    float x0 = v0 / den, x1 = v1 / den;
    dcat[(size_t)row * 64 + lane] = 1.0f / (1.0f + expf(-x0));
    dcat[(size_t)row * 64 + lane + 32] = 1.0f / (1.0f + expf(-x1));
}

// ---------------- transpose ----------------
__global__ void transpose64_kernel(const float* __restrict__ W, float* __restrict__ WT) {
    for (int t = threadIdx.x; t < 64 * 64; t += blockDim.x) {
        int i = t >> 6, j = t & 63;
        WT[j * 64 + i] = W[t];
    }
}

// ---------------- bilinear outputs (warp per logical row, 8192 rows) ----------
__global__ void bilin_warp_kernel(const float* __restrict__ qcat, const float* __restrict__ u,
                                  const float* __restrict__ b, float* __restrict__ ret,
                                  float* __restrict__ reta) {
    int row = blockIdx.x * 8 + (threadIdx.x >> 5);
    int lane = threadIdx.x & 31;
    if (row >= 2 * NN) return;
    int r = row & (NN - 1);
    const float* ur = u + (size_t)row * 64;
    const float* xpl = qcat + (size_t)(2 * NN + r) * 64;
    const float* xmi = qcat + (size_t)(3 * NN + r) * 64;
    float v0, v1;
    if (row < NN) {
        v0 = xpl[lane] * ur[lane] + xpl[lane + 32] * ur[lane + 32];
        v1 = xmi[lane] * ur[lane] + xmi[lane + 32] * ur[lane + 32];
    } else {
        v0 = xmi[lane] * ur[lane] + xmi[lane + 32] * ur[lane + 32];
        v1 = xpl[lane] * ur[lane] + xpl[lane + 32] * ur[lane + 32];
    }
    #pragma unroll
    for (int o = 16; o > 0; o >>= 1) {
        v0 += __shfl_down_sync(FULLM, v0, o);
        v1 += __shfl_down_sync(FULLM, v1, o);
    }
    if (lane == 0) {
        float* dst = (row < NN) ? ret : reta;
        dst[(size_t)r * 2 + 0] = v0 + b[0];
        dst[(size_t)r * 2 + 1] = v1 + b[0];
    }
}

// ---------------- host ----------------
static void* sym(const void* s) {
    void* p = nullptr;
    cudaGetSymbolAddress(&p, s);
    return p;
}

extern "C" void kernel_launch(void* const* d_in, const int* in_sizes, int n_in,
                              void* d_out, int out_size) {
    const float* feat   = (const float*)d_in[0];
    const float* feat_a = (const float*)d_in[1];
    const float* adj    = (const float*)d_in[2];
    const float* gn     = (const float*)d_in[3];
    const float* w1     = (const float*)d_in[4];
    const float* w2     = (const float*)d_in[5];
    const float* attW   = (const float*)d_in[6];
    const float* a_src  = (const float*)d_in[7];
    const float* a_dst  = (const float*)d_in[8];
    const float* mW1 = (const float*)d_in[9];  const float* mb1 = (const float*)d_in[10];
    const float* mW2 = (const float*)d_in[11]; const float* mb2 = (const float*)d_in[12];
    const float* mW3 = (const float*)d_in[13]; const float* mb3 = (const float*)d_in[14];
    const float* dW1 = (const float*)d_in[15]; const float* db1 = (const float*)d_in[16];
    const float* dW2 = (const float*)d_in[17]; const float* db2 = (const float*)d_in[18];
    const float* bilW = (const float*)d_in[19];
    const float* bilb = (const float*)d_in[20];

    float* out      = (float*)d_out;
    float* out_h    = out + (size_t)NN * FOUT;
    float* out_ret  = out_h + (size_t)NN * FIN;
    float* out_reta = out_ret + (size_t)NN * 2;

    float* X    = (float*)sym(g_X);
    float* Wh   = (float*)sym(g_Wh);
    float* sv   = (float*)sym(g_s);
    float* dv   = (float*)sym(g_d);
    float* att  = (float*)sym(g_att);
    float* t1   = (float*)sym(g_t1);
    float* t2   = (float*)sym(g_t2);
    float* adjz = (float*)sym(g_adjz);
    float* dcat = (float*)sym(g_dcat);
    float* dh   = (float*)sym(g_dh);
    float* qcat = (float*)sym(g_qcat);
    float* u    = (float*)sym(g_u);
    float* part = (float*)sym(g_part);
    float* WT   = (float*)sym(g_WT);
    float* Bhi  = (float*)sym(g_Bhi);
    float* Blo  = (float*)sym(g_Blo);
    int* aidx = (int*)sym(g_adj_idx); int* acnt = (int*)sym(g_adj_cnt);
    int* gidx = (int*)sym(g_gn_idx);  int* gcnt = (int*)sym(g_gn_cnt);

    const int M2 = 2 * NN;   // 8192
    const int M4 = 4 * NN;   // 16384
    const long long PS = (long long)NN * FOUT;

    // 1. sparse lists (one launch) + weight preprocessing
    build_list_kernel<<<dim3(NN, 2), 256>>>(adj, aidx, acnt, gn, gidx, gcnt);
    transpose64_kernel<<<1, 256>>>(bilW, WT);
    {
        SplitArgs sa;
        sa.src[0] = w1;   sa.n[0] = FIN * FOUT;  sa.off[0] = OFF_W1;
        sa.src[1] = w2;   sa.n[1] = FOUT * FIN;  sa.off[1] = OFF_W2;
        sa.src[2] = attW; sa.n[2] = 64 * 64;     sa.off[2] = OFF_ATTW;
        sa.src[3] = mW1;  sa.n[3] = 64 * 256;    sa.off[3] = OFF_MW1;
        sa.src[4] = mW2;  sa.n[4] = 256 * 128;   sa.off[4] = OFF_MW2;
        sa.src[5] = mW3;  sa.n[5] = 128 * 64;    sa.off[5] = OFF_MW3;
        sa.src[6] = dW1;  sa.n[6] = 64 * 128;    sa.off[6] = OFF_DW1;
        sa.src[7] = dW2;  sa.n[7] = 128 * 64;    sa.off[7] = OFF_DW2;
        sa.src[8] = WT;   sa.n[8] = 64 * 64;     sa.off[8] = OFF_WT;
        split_kernel<<<dim3((FIN * FOUT + 255) / 256, 9), 256>>>(sa, Bhi, Blo);
    }

    // 2. X = [feat; feat_a] @ w1  (plain tf32, BM=128, split-K=4 -> 256 CTAs)
    gemm_tc<1, 4, 32><<<dim3(1, NN / 128, 2 * KSPL), 128>>>(
        feat, feat_a, Bhi + OFF_W1, Blo + OFF_W1, nullptr, part, nullptr,
        NN, FOUT, FIN, 752, KSPL, PS, 0);
    reduce_part_kernel<<<(M2 * FOUT + 255) / 256, 256>>>(part, X);

    // 3. batched GAT + MLP over 8192 rows (3xtf32, BM=64, 64 threads)
    gemm_tc<3, 2, 16><<<dim3(1, M2 / 64, 1), 64>>>(X, nullptr, Bhi + OFF_ATTW, Blo + OFF_ATTW,
                                                   nullptr, Wh, nullptr, M2, 64, 64, 64, 1, 0, 0);
    sd_kernel<<<M2 / 8, 256>>>(Wh, a_src, a_dst, sv, dv);
    att_warp_kernel<<<M2 / 8, 256>>>(aidx, acnt, sv, dv, Wh, att);
    gemm_tc<3, 2, 16><<<dim3(4, M2 / 64, 1), 64>>>(att, nullptr, Bhi + OFF_MW1, Blo + OFF_MW1,
                                                   mb1, t1, nullptr, M2, 256, 64, 64, 1, 0, 1);
    gemm_tc<3, 2, 16><<<dim3(2, M2 / 64, 1), 64>>>(t1, nullptr, Bhi + OFF_MW2, Blo + OFF_MW2,
                                                   mb2, t2, nullptr, M2, 128, 256, 256, 1, 0, 1);
    // MLP3: raw -> out (rows < NN = hiden_emb/z), relu -> dcat[8192..16383] (emb; emba)
    gemm_tc<3, 2, 16><<<dim3(1, M2 / 64, 1), 64>>>(t2, nullptr, Bhi + OFF_MW3, Blo + OFF_MW3,
                                                   mb3, out, dcat + (size_t)M2 * FOUT,
                                                   M2, 64, 128, 128, 1, 0, 3);

    // 4. h = (adj @ z) @ w2  (z read from d_out; plain tf32, BM=128)
    agg_warp_kernel<<<NN / 8, 256>>>(aidx, acnt, out, adjz);
    gemm_tc<1, 4, 32><<<dim3((FIN + 63) / 64, NN / 128, 1), 128>>>(
        adjz, nullptr, Bhi + OFF_W2, Blo + OFF_W2, nullptr, out_h, nullptr,
        NN, FIN, FOUT, FOUT, 1, 0, 0);

    // 5. readouts -> dcat[0..8191] = [gv; gva]
    readout_warp_kernel<<<M2 / 8, 256>>>(gidx, gcnt, dcat);

    // 6. discriminator MLP over all 16384 rows -> qcat = [dc; dca; dpl; dmi]
    gemm_tc<3, 2, 16><<<dim3(2, M4 / 64, 1), 64>>>(dcat, nullptr, Bhi + OFF_DW1, Blo + OFF_DW1,
                                                   db1, dh, nullptr, M4, 128, 64, 64, 1, 0, 1);
    gemm_tc<3, 2, 16><<<dim3(1, M4 / 64, 1), 64>>>(dh, nullptr, Bhi + OFF_DW2, Blo + OFF_DW2,
                                                   db2, qcat, nullptr, M4, 64, 128, 128, 1, 0, 0);

    // 7. bilinear
    gemm_tc<3, 2, 16><<<dim3(1, M2 / 64, 1), 64>>>(qcat, nullptr, Bhi + OFF_WT, Blo + OFF_WT,
                                                   nullptr, u, nullptr, M2, 64, 64, 64, 1, 0, 0);
    bilin_warp_kernel<<<M2 / 8, 256>>>(qcat, u, bilb, out_ret, out_reta);
}

// round 9
// speedup vs baseline: 1.1071x; 1.1071x over previous
#include <cuda_runtime.h>
#include <math.h>
#include <mma.h>

using namespace nvcuda;

#define NN 4096
#define FIN 3000
#define FOUT 64
#define MAXNNZ 512
#define KSPLIT 8
#define FULLM 0xffffffffu

// ---------------- scratch (static device memory; no allocation) ----------------
__device__ float g_X   [2*NN*FOUT];      // [X1; X1a]
__device__ float g_Wh  [2*NN*FOUT];
__device__ float g_s   [2*NN];
__device__ float g_d   [2*NN];
__device__ float g_att [2*NN*FOUT];
__device__ float g_t1  [2*NN*256];
__device__ float g_t2  [2*NN*128];
__device__ float g_adjz[NN*FOUT];
__device__ float g_dcat[4*NN*FOUT];      // [gv; gva; emb; emba]
__device__ float g_dh  [4*NN*128];
__device__ float g_qcat[4*NN*FOUT];      // [dc; dca; dpl; dmi]
__device__ float g_u   [2*NN*FOUT];      // [u; ua]
__device__ float g_part[2*KSPLIT*NN*FOUT];
__device__ float g_WT  [FOUT*FOUT];
__device__ int   g_adj_idx[NN*MAXNNZ];
__device__ int   g_adj_cnt[NN];
__device__ int   g_gn_idx [NN*MAXNNZ];
__device__ int   g_gn_cnt [NN];

// precomputed tf32 hi/lo weight buffers (concatenated)
#define OFF_W1   0
#define OFF_W2   192000
#define OFF_ATTW 384000
#define OFF_MW1  388096
#define OFF_MW2  404480
#define OFF_MW3  437248
#define OFF_DW1  445440
#define OFF_DW2  453632
#define OFF_WT   461824
#define SPLIT_TOTAL 465920
__device__ float g_Bhi[SPLIT_TOTAL];
__device__ float g_Blo[SPLIT_TOTAL];

__device__ __forceinline__ float t32(float x) { return wmma::__float_to_tf32(x); }

// ---------------- weight hi/lo split (one launch, 9 segments) -----------------
struct SplitArgs {
    const float* src[9];
    int n[9];
    int off[9];
};
__global__ void split_kernel(SplitArgs a, float* __restrict__ hi, float* __restrict__ lo) {
    int seg = blockIdx.y;
    int i = blockIdx.x * 256 + threadIdx.x;
    if (i < a.n[seg]) {
        float x = a.src[seg][i];
        float h = t32(x);
        hi[a.off[seg] + i] = h;
        lo[a.off[seg] + i] = t32(x - h);
    }
}

// ---------------- build sparse row lists (both matrices, one launch) ----------
__global__ void build_list_kernel(const float* __restrict__ matA, int* __restrict__ idxA,
                                  int* __restrict__ cntA,
                                  const float* __restrict__ matB, int* __restrict__ idxB,
                                  int* __restrict__ cntB) {
    int row = blockIdx.x;
    const float* mat = blockIdx.y ? matB : matA;
    int* idx = blockIdx.y ? idxB : idxA;
    int* cnt = blockIdx.y ? cntB : cntA;
    int tid = threadIdx.x;
    int wid = tid >> 5, lane = tid & 31;
    const float4* r4 = (const float4*)(mat + (size_t)row * NN);
    __shared__ int wsum[8];
    __shared__ int woff[8];
    float v[16];
    #pragma unroll
    for (int q = 0; q < 4; q++) {
        float4 x = r4[tid * 4 + q];
        v[q * 4 + 0] = x.x; v[q * 4 + 1] = x.y; v[q * 4 + 2] = x.z; v[q * 4 + 3] = x.w;
    }
    int base = tid * 16;
    int c = 0;
    #pragma unroll
    for (int j = 0; j < 16; j++) c += (v[j] != 0.0f);
    int inc = c;
    #pragma unroll
    for (int o = 1; o < 32; o <<= 1) {
        int t = __shfl_up_sync(FULLM, inc, o);
        if (lane >= o) inc += t;
    }
    if (lane == 31) wsum[wid] = inc;
    __syncthreads();
    if (tid < 8) {
        int t = wsum[tid];
        int iv = t;
        #pragma unroll
        for (int o = 1; o < 8; o <<= 1) {
            int u = __shfl_up_sync(0xffu, iv, o);
            if (tid >= o) iv += u;
        }
        woff[tid] = iv - t;
        if (tid == 7) cnt[row] = iv;
    }
    __syncthreads();
    int o = woff[wid] + inc - c;
    int* dst = idx + (size_t)row * MAXNNZ;
    #pragma unroll
    for (int j = 0; j < 16; j++) {
        if (v[j] != 0.0f) dst[o++] = base + j;
    }
}

// ---------------- tf32 WMMA GEMM, templated tile, register prefetch -----------
// C = act(A[M,K] @ B[K,N] + bias). BM=WARPS*16, BN=64, threads=WARPS*32.
// PREC=3: 3xtf32 compensated; PREC=1: plain tf32 (launch_bounds allows 3 CTAs).
// split-K via blockIdx.z: kz = bz % kspl; bz >= kspl uses A2.
// act: 0 none, 1 relu, 2 raw->C + relu->C2, 3 raw->C only rows<NN + relu->C2.
template<int PREC, int WARPS, int BK>
__global__ __launch_bounds__(WARPS * 32, (WARPS == 8) ? (PREC == 1 ? 3 : 2) : 4)
void gemm_tc(const float* __restrict__ A, const float* __restrict__ A2,
             const float* __restrict__ Bhi, const float* __restrict__ Blo,
             const float* __restrict__ bias, float* __restrict__ C,
             float* __restrict__ C2, int M, int N, int K,
             int kChunk, int kspl, long long partStride, int act) {
    constexpr int BM = WARPS * 16;
    constexpr int TPB = WARPS * 32;
    constexpr int CPT = BM * BK / TPB;     // A cols per thread
    constexpr int AFR = CPT / 4;           // A float4s per thread
    constexpr int BROWS = TPB / 16;        // B k-rows covered per pass
    constexpr int BITER = BK / BROWS;      // B float4s per thread
    constexpr int LDA = BK + 4;

    int bz = blockIdx.z;
    int kz = bz % kspl;
    const float* Asrc = (bz < kspl) ? A : A2;
    int k0 = kz * kChunk;
    int k1 = min(K, k0 + kChunk);
    float* Cp = C + (long long)bz * partStride;
    int row0 = blockIdx.y * BM;
    int col0 = blockIdx.x * 64;
    int tid = threadIdx.x;
    int wid = tid >> 5;
    int lane = tid & 31;

    __shared__ float Ah[BM][LDA];
    __shared__ float Al[PREC == 3 ? BM : 1][LDA];
    __shared__ float Bh[BK][72];
    __shared__ float Bl[PREC == 3 ? BK : 1][72];
    __shared__ float Cb[WARPS][256];

    wmma::fragment<wmma::accumulator, 16, 16, 8, float> acc[4];
    #pragma unroll
    for (int f = 0; f < 4; f++) wmma::fill_fragment(acc[f], 0.0f);

    // A: 2 threads per row, CPT contiguous cols each. All K, k1 multiples of 4.
    int ar = tid >> 1;
    int acb = (tid & 1) * CPT;
    const float* Arow = Asrc + (size_t)(row0 + ar) * K;
    // B: one float4 per (k-row, 4 cols) slot.
    int bn = (tid & 15) * 4;
    int bkb = tid >> 4;
    int gnB = col0 + bn;

    float4 aR[AFR], bhR[BITER], blR[BITER];
    const float4 f4z = make_float4(0.f, 0.f, 0.f, 0.f);

    auto loadTiles = [&](int kk) {
        #pragma unroll
        for (int v = 0; v < AFR; v++) {
            int gk = kk + acb + v * 4;
            aR[v] = (gk < k1) ? *(const float4*)(Arow + gk) : f4z;
        }
        #pragma unroll
        for (int i = 0; i < BITER; i++) {
            int gkb = kk + bkb + i * BROWS;
            bhR[i] = f4z;
            if (PREC == 3) blR[i] = f4z;
            if (gkb < k1 && gnB < N) {
                bhR[i] = *(const float4*)(Bhi + (size_t)gkb * N + gnB);
                if (PREC == 3) blR[i] = *(const float4*)(Blo + (size_t)gkb * N + gnB);
            }
        }
    };
    auto storeTiles = [&]() {
        #pragma unroll
        for (int v = 0; v < AFR; v++) {
            int c = acb + v * 4;
            float* dh = &Ah[ar][c];
            float* dl = &Al[PREC == 3 ? ar : 0][c];
            float h;
            h = t32(aR[v].x); dh[0] = h; if (PREC == 3) dl[0] = t32(aR[v].x - h);
            h = t32(aR[v].y); dh[1] = h; if (PREC == 3) dl[1] = t32(aR[v].y - h);
            h = t32(aR[v].z); dh[2] = h; if (PREC == 3) dl[2] = t32(aR[v].z - h);
            h = t32(aR[v].w); dh[3] = h; if (PREC == 3) dl[3] = t32(aR[v].w - h);
        }
        #pragma unroll
        for (int i = 0; i < BITER; i++) {
            *(float4*)&Bh[bkb + i * BROWS][bn] = bhR[i];
            if (PREC == 3) *(float4*)&Bl[bkb + i * BROWS][bn] = blR[i];
        }
    };

    loadTiles(k0);
    for (int kk = k0; kk < k1; kk += BK) {
        storeTiles();
        __syncthreads();
        int nk = kk + BK;
        if (nk < k1) loadTiles(nk);   // prefetch; latency hidden by mma below
        #pragma unroll
        for (int ks = 0; ks < BK; ks += 8) {
            wmma::fragment<wmma::matrix_a, 16, 16, 8, wmma::precision::tf32, wmma::row_major> ah, al;
            wmma::load_matrix_sync(ah, &Ah[wid * 16][ks], LDA);
            if (PREC == 3) wmma::load_matrix_sync(al, &Al[wid * 16][ks], LDA);
            #pragma unroll
            for (int f = 0; f < 4; f++) {
                wmma::fragment<wmma::matrix_b, 16, 16, 8, wmma::precision::tf32, wmma::row_major> bh, bl;
                wmma::load_matrix_sync(bh, &Bh[ks][f * 16], 72);
                if (PREC == 3) {
                    wmma::load_matrix_sync(bl, &Bl[ks][f * 16], 72);
                    wmma::mma_sync(acc[f], ah, bl, acc[f]);
                    wmma::mma_sync(acc[f], al, bh, acc[f]);
                }
                wmma::mma_sync(acc[f], ah, bh, acc[f]);
            }
        }
        __syncthreads();
    }

    int r0 = row0 + wid * 16;
    #pragma unroll
    for (int f = 0; f < 4; f++) {
        int c0 = col0 + f * 16;
        __syncwarp();
        wmma::store_matrix_sync(&Cb[wid][0], acc[f], 16, wmma::mem_row_major);
        __syncwarp();
        for (int e = lane; e < 256; e += 32) {
            int rr = e >> 4, cc = e & 15;
            int c = c0 + cc;
            if (c < N) {
                float v = Cb[wid][e];
                if (bias) v += bias[c];
                int gr = r0 + rr;
                size_t oi = (size_t)gr * N + c;
                if (act == 0) {
                    Cp[oi] = v;
                } else if (act == 1) {
                    Cp[oi] = fmaxf(v, 0.0f);
                } else if (act == 2) {
                    Cp[oi] = v;
                    C2[oi] = fmaxf(v, 0.0f);
                } else {  // act == 3
                    if (gr < NN) Cp[oi] = v;
                    C2[oi] = fmaxf(v, 0.0f);
                }
            }
        }
    }
}

// fused split-K reduce over both feat GEMMs -> X [2*NN, FOUT]
__global__ void reduce_part_kernel(const float* __restrict__ part, float* __restrict__ out) {
    int i = blockIdx.x * blockDim.x + threadIdx.x;
    const int HALF = NN * FOUT;
    if (i < 2 * HALF) {
        int h = i >= HALF;
        const float* base = part + (size_t)h * KSPLIT * HALF;
        int j = i - h * HALF;
        float s = 0.0f;
        #pragma unroll
        for (int z = 0; z < KSPLIT; z++) s += base[(size_t)z * HALF + j];
        out[i] = s;
    }
}

// ---------------- s = Wh@a_src, d = Wh@a_dst (warp per row, 8192 rows) --------
__global__ void sd_kernel(const float* __restrict__ Wh, const float* __restrict__ a_src,
                          const float* __restrict__ a_dst, float* __restrict__ s,
                          float* __restrict__ d) {
    int row = blockIdx.x * 8 + (threadIdx.x >> 5);
    int lane = threadIdx.x & 31;
    if (row < 2 * NN) {
        const float* w = Wh + (size_t)row * 64;
        float vs = w[lane] * a_src[lane] + w[lane + 32] * a_src[lane + 32];
        float vd = w[lane] * a_dst[lane] + w[lane + 32] * a_dst[lane + 32];
        #pragma unroll
        for (int o = 16; o > 0; o >>= 1) {
            vs += __shfl_down_sync(FULLM, vs, o);
            vd += __shfl_down_sync(FULLM, vd, o);
        }
        if (lane == 0) { s[row] = vs; d[row] = vd; }
    }
}

// ---------------- warp-per-row attention (online softmax), 8192 rows ----------
__global__ void att_warp_kernel(const int* __restrict__ idx, const int* __restrict__ cnt,
                                const float* __restrict__ s, const float* __restrict__ d,
                                const float* __restrict__ Wh, float* __restrict__ out) {
    int row = blockIdx.x * 8 + (threadIdx.x >> 5);
    int lane = threadIdx.x & 31;
    if (row >= 2 * NN) return;
    int grow = row & (NN - 1);
    int off = row & NN;
    int n = cnt[grow];
    const int* lst = idx + (size_t)grow * MAXNNZ;
    float si = s[row];
    float m = -3.4e38f, ssum = 0.0f, a0 = 0.0f, a1 = 0.0f;
    for (int base = 0; base < n; base += 32) {
        int t = base + lane;
        int j = 0;
        float e = -3.4e38f;
        if (t < n) {
            j = lst[t];
            float v = si + d[j + off];
            e = v > 0.0f ? v : 0.2f * v;
        }
        float cm = e;
        #pragma unroll
        for (int o = 16; o > 0; o >>= 1) cm = fmaxf(cm, __shfl_xor_sync(FULLM, cm, o));
        float nm = fmaxf(m, cm);
        float scale = expf(m - nm);
        a0 *= scale; a1 *= scale; ssum *= scale;
        float w = (t < n) ? expf(e - nm) : 0.0f;
        float cs = w;
        #pragma unroll
        for (int o = 16; o > 0; o >>= 1) cs += __shfl_xor_sync(FULLM, cs, o);
        ssum += cs;
        int lim = min(32, n - base);
        for (int q = 0; q < lim; q++) {
            float wq = __shfl_sync(FULLM, w, q);
            int jq = __shfl_sync(FULLM, j, q);
            const float* r = Wh + (size_t)(jq + off) * 64;
            a0 += wq * r[lane];
            a1 += wq * r[lane + 32];
        }
        m = nm;
    }
    float inv = 1.0f / ssum;
    out[(size_t)row * 64 + lane] = a0 * inv;
    out[(size_t)row * 64 + lane + 32] = a1 * inv;
}

// ---------------- adjz = adj @ z (warp per row; z lives in d_out) -------------
__global__ void agg_warp_kernel(const int* __restrict__ idx, const int* __restrict__ cnt,
                                const float* __restrict__ z, float* __restrict__ out) {
    int row = blockIdx.x * 8 + (threadIdx.x >> 5);
    int lane = threadIdx.x & 31;
    if (row >= NN) return;
    int n = cnt[row];
    const int* lst = idx + (size_t)row * MAXNNZ;
    float a0 = 0.0f, a1 = 0.0f;
    for (int base = 0; base < n; base += 32) {
        int t = base + lane;
        int j = (t < n) ? lst[t] : 0;
        int lim = min(32, n - base);
        for (int q = 0; q < lim; q++) {
            int jq = __shfl_sync(FULLM, j, q);
            const float* r = z + (size_t)jq * 64;
            a0 += r[lane];
            a1 += r[lane + 32];
        }
    }
    out[(size_t)row * 64 + lane] = a0;
    out[(size_t)row * 64 + lane + 32] = a1;
}

// ---------------- warp-per-row readout: mean, L2-norm, sigmoid (8192 rows) ----
__global__ void readout_warp_kernel(const int* __restrict__ idx, const int* __restrict__ cnt,
                                    float* __restrict__ dcat) {
    int row = blockIdx.x * 8 + (threadIdx.x >> 5);
    int lane = threadIdx.x & 31;
    if (row >= 2 * NN) return;
    int grow = row & (NN - 1);
    int n = cnt[grow];
    const int* lst = idx + (size_t)grow * MAXNNZ;
    int off = (row < NN) ? 2 * NN : 3 * NN;
    float a0 = 0.0f, a1 = 0.0f;
    for (int base = 0; base < n; base += 32) {
        int t = base + lane;
        int j = (t < n) ? lst[t] : 0;
        int lim = min(32, n - base);
        for (int q = 0; q < lim; q++) {
            int jq = __shfl_sync(FULLM, j, q);
            const float* r = dcat + (size_t)(off + jq) * 64;
            a0 += r[lane];
            a1 += r[lane + 32];
        }
    }
    float invn = 1.0f / (float)n;
    float v0 = a0 * invn, v1 = a1 * invn;
    float ss = v0 * v0 + v1 * v1;
    #pragma unroll
    for (int o = 16; o > 0; o >>= 1) ss += __shfl_xor_sync(FULLM, ss, o);
    float den = fmaxf(sqrtf(ss), 1e-12f);
    float x0 = v0 / den, x1 = v1 / den;
    dcat[(size_t)row * 64 + lane] = 1.0f / (1.0f + expf(-x0));
    dcat[(size_t)row * 64 + lane + 32] = 1.0f / (1.0f + expf(-x1));
}

// ---------------- transpose ----------------
__global__ void transpose64_kernel(const float* __restrict__ W, float* __restrict__ WT) {
    for (int t = threadIdx.x; t < 64 * 64; t += blockDim.x) {
        int i = t >> 6, j = t & 63;
        WT[j * 64 + i] = W[t];
    }
}

// ---------------- bilinear outputs (warp per logical row, 8192 rows) ----------
__global__ void bilin_warp_kernel(const float* __restrict__ qcat, const float* __restrict__ u,
                                  const float* __restrict__ b, float* __restrict__ ret,
                                  float* __restrict__ reta) {
    int row = blockIdx.x * 8 + (threadIdx.x >> 5);
    int lane = threadIdx.x & 31;
    if (row >= 2 * NN) return;
    int r = row & (NN - 1);
    const float* ur = u + (size_t)row * 64;
    const float* xpl = qcat + (size_t)(2 * NN + r) * 64;
    const float* xmi = qcat + (size_t)(3 * NN + r) * 64;
    float v0, v1;
    if (row < NN) {
        v0 = xpl[lane] * ur[lane] + xpl[lane + 32] * ur[lane + 32];
        v1 = xmi[lane] * ur[lane] + xmi[lane + 32] * ur[lane + 32];
    } else {
        v0 = xmi[lane] * ur[lane] + xmi[lane + 32] * ur[lane + 32];
        v1 = xpl[lane] * ur[lane] + xpl[lane + 32] * ur[lane + 32];
    }
    #pragma unroll
    for (int o = 16; o > 0; o >>= 1) {
        v0 += __shfl_down_sync(FULLM, v0, o);
        v1 += __shfl_down_sync(FULLM, v1, o);
    }
    if (lane == 0) {
        float* dst = (row < NN) ? ret : reta;
        dst[(size_t)r * 2 + 0] = v0 + b[0];
        dst[(size_t)r * 2 + 1] = v1 + b[0];
    }
}

// ---------------- host ----------------
static void* sym(const void* s) {
    void* p = nullptr;
    cudaGetSymbolAddress(&p, s);
    return p;
}

extern "C" void kernel_launch(void* const* d_in, const int* in_sizes, int n_in,
                              void* d_out, int out_size) {
    const float* feat   = (const float*)d_in[0];
    const float* feat_a = (const float*)d_in[1];
    const float* adj    = (const float*)d_in[2];
    const float* gn     = (const float*)d_in[3];
    const float* w1     = (const float*)d_in[4];
    const float* w2     = (const float*)d_in[5];
    const float* attW   = (const float*)d_in[6];
    const float* a_src  = (const float*)d_in[7];
    const float* a_dst  = (const float*)d_in[8];
    const float* mW1 = (const float*)d_in[9];  const float* mb1 = (const float*)d_in[10];
    const float* mW2 = (const float*)d_in[11]; const float* mb2 = (const float*)d_in[12];
    const float* mW3 = (const float*)d_in[13]; const float* mb3 = (const float*)d_in[14];
    const float* dW1 = (const float*)d_in[15]; const float* db1 = (const float*)d_in[16];
    const float* dW2 = (const float*)d_in[17]; const float* db2 = (const float*)d_in[18];
    const float* bilW = (const float*)d_in[19];
    const float* bilb = (const float*)d_in[20];

    float* out      = (float*)d_out;
    float* out_h    = out + (size_t)NN * FOUT;
    float* out_ret  = out_h + (size_t)NN * FIN;
    float* out_reta = out_ret + (size_t)NN * 2;

    float* X    = (float*)sym(g_X);
    float* Wh   = (float*)sym(g_Wh);
    float* sv   = (float*)sym(g_s);
    float* dv   = (float*)sym(g_d);
    float* att  = (float*)sym(g_att);
    float* t1   = (float*)sym(g_t1);
    float* t2   = (float*)sym(g_t2);
    float* adjz = (float*)sym(g_adjz);
    float* dcat = (float*)sym(g_dcat);
    float* dh   = (float*)sym(g_dh);
    float* qcat = (float*)sym(g_qcat);
    float* u    = (float*)sym(g_u);
    float* part = (float*)sym(g_part);
    float* WT   = (float*)sym(g_WT);
    float* Bhi  = (float*)sym(g_Bhi);
    float* Blo  = (float*)sym(g_Blo);
    int* aidx = (int*)sym(g_adj_idx); int* acnt = (int*)sym(g_adj_cnt);
    int* gidx = (int*)sym(g_gn_idx);  int* gcnt = (int*)sym(g_gn_cnt);

    const int M2 = 2 * NN;   // 8192
    const int M4 = 4 * NN;   // 16384
    const long long PS = (long long)NN * FOUT;

    // 1. sparse lists (one launch) + weight preprocessing
    build_list_kernel<<<dim3(NN, 2), 256>>>(adj, aidx, acnt, gn, gidx, gcnt);
    transpose64_kernel<<<1, 256>>>(bilW, WT);
    {
        SplitArgs sa;
        sa.src[0] = w1;   sa.n[0] = FIN * FOUT;  sa.off[0] = OFF_W1;
        sa.src[1] = w2;   sa.n[1] = FOUT * FIN;  sa.off[1] = OFF_W2;
        sa.src[2] = attW; sa.n[2] = 64 * 64;     sa.off[2] = OFF_ATTW;
        sa.src[3] = mW1;  sa.n[3] = 64 * 256;    sa.off[3] = OFF_MW1;
        sa.src[4] = mW2;  sa.n[4] = 256 * 128;   sa.off[4] = OFF_MW2;
        sa.src[5] = mW3;  sa.n[5] = 128 * 64;    sa.off[5] = OFF_MW3;
        sa.src[6] = dW1;  sa.n[6] = 64 * 128;    sa.off[6] = OFF_DW1;
        sa.src[7] = dW2;  sa.n[7] = 128 * 64;    sa.off[7] = OFF_DW2;
        sa.src[8] = WT;   sa.n[8] = 64 * 64;     sa.off[8] = OFF_WT;
        split_kernel<<<dim3((FIN * FOUT + 255) / 256, 9), 256>>>(sa, Bhi, Blo);
    }

    // 2. X = [feat; feat_a] @ w1  (plain tf32, BM=128/BK=32, split-K=8, 3 CTAs/SM)
    gemm_tc<1, 8, 32><<<dim3(1, NN / 128, 2 * KSPLIT), 256>>>(
        feat, feat_a, Bhi + OFF_W1, Blo + OFF_W1, nullptr, part, nullptr,
        NN, FOUT, FIN, 376, KSPLIT, PS, 0);
    reduce_part_kernel<<<(M2 * FOUT + 255) / 256, 256>>>(part, X);

    // 3. batched GAT + MLP over 8192 rows (3xtf32, BM=64)
    gemm_tc<3, 4, 16><<<dim3(1, M2 / 64, 1), 128>>>(X, nullptr, Bhi + OFF_ATTW, Blo + OFF_ATTW,
                                                    nullptr, Wh, nullptr, M2, 64, 64, 64, 1, 0, 0);
    sd_kernel<<<M2 / 8, 256>>>(Wh, a_src, a_dst, sv, dv);
    att_warp_kernel<<<M2 / 8, 256>>>(aidx, acnt, sv, dv, Wh, att);
    gemm_tc<3, 4, 16><<<dim3(4, M2 / 64, 1), 128>>>(att, nullptr, Bhi + OFF_MW1, Blo + OFF_MW1,
                                                    mb1, t1, nullptr, M2, 256, 64, 64, 1, 0, 1);
    gemm_tc<3, 4, 16><<<dim3(2, M2 / 64, 1), 128>>>(t1, nullptr, Bhi + OFF_MW2, Blo + OFF_MW2,
                                                    mb2, t2, nullptr, M2, 128, 256, 256, 1, 0, 1);
    // MLP3: raw -> out (rows < NN = hiden_emb/z), relu -> dcat[8192..16383] (emb; emba)
    gemm_tc<3, 4, 16><<<dim3(1, M2 / 64, 1), 128>>>(t2, nullptr, Bhi + OFF_MW3, Blo + OFF_MW3,
                                                    mb3, out, dcat + (size_t)M2 * FOUT,
                                                    M2, 64, 128, 128, 1, 0, 3);

    // 4. h = (adj @ z) @ w2  (z read from d_out; plain tf32, 3 CTAs/SM)
    agg_warp_kernel<<<NN / 8, 256>>>(aidx, acnt, out, adjz);
    gemm_tc<1, 8, 32><<<dim3((FIN + 63) / 64, NN / 128, 1), 256>>>(
        adjz, nullptr, Bhi + OFF_W2, Blo + OFF_W2, nullptr, out_h, nullptr,
        NN, FIN, FOUT, FOUT, 1, 0, 0);

    // 5. readouts -> dcat[0..8191] = [gv; gva]
    readout_warp_kernel<<<M2 / 8, 256>>>(gidx, gcnt, dcat);

    // 6. discriminator MLP over all 16384 rows -> qcat = [dc; dca; dpl; dmi]
    gemm_tc<3, 4, 16><<<dim3(2, M4 / 64, 1), 128>>>(dcat, nullptr, Bhi + OFF_DW1, Blo + OFF_DW1,
                                                    db1, dh, nullptr, M4, 128, 64, 64, 1, 0, 1);
    gemm_tc<3, 4, 16><<<dim3(1, M4 / 64, 1), 128>>>(dh, nullptr, Bhi + OFF_DW2, Blo + OFF_DW2,
                                                    db2, qcat, nullptr, M4, 64, 128, 128, 1, 0, 0);

    // 7. bilinear
    gemm_tc<3, 4, 16><<<dim3(1, M2 / 64, 1), 128>>>(qcat, nullptr, Bhi + OFF_WT, Blo + OFF_WT,
                                                    nullptr, u, nullptr, M2, 64, 64, 64, 1, 0, 0);
    bilin_warp_kernel<<<M2 / 8, 256>>>(qcat, u, bilb, out_ret, out_reta);
}

// round 10
// speedup vs baseline: 1.1909x; 1.0757x over previous
#include <cuda_runtime.h>
#include <math.h>
#include <mma.h>

using namespace nvcuda;

#define NN 4096
#define FIN 3000
#define FOUT 64
#define MAXNNZ 512
#define KSPL 9
#define FULLM 0xffffffffu

// ---------------- scratch (static device memory; no allocation) ----------------
__device__ float g_w1p [FIN*FOUT];       // w1 @ attW
__device__ float g_Wh  [2*NN*FOUT];
__device__ float g_s   [2*NN];
__device__ float g_d   [2*NN];
__device__ float g_att [2*NN*FOUT];
__device__ float g_t1  [2*NN*256];
__device__ float g_t2  [2*NN*128];
__device__ float g_adjz[NN*FOUT];
__device__ float g_dcat[4*NN*FOUT];      // [gv; gva; emb; emba]
__device__ float g_dh  [4*NN*128];
__device__ float g_qcat[4*NN*FOUT];      // [dc; dca; dpl; dmi]
__device__ float g_u   [2*NN*FOUT];      // [u; ua]
__device__ float g_part[2*KSPL*NN*FOUT];
__device__ int   g_adj_idx[NN*MAXNNZ];
__device__ int   g_adj_cnt[NN];
__device__ int   g_gn_idx [NN*MAXNNZ];
__device__ int   g_gn_cnt [NN];

// precomputed tf32 hi/lo weight buffers (concatenated)
#define OFF_W1   0
#define OFF_W2   192000
#define OFF_MW1  384000
#define OFF_MW2  400384
#define OFF_MW3  433152
#define OFF_DW1  441344
#define OFF_DW2  449536
#define OFF_WT   457728
#define SPLIT_TOTAL 461824
__device__ float g_Bhi[SPLIT_TOTAL];
__device__ float g_Blo[SPLIT_TOTAL];

__device__ __forceinline__ float t32(float x) { return wmma::__float_to_tf32(x); }

// ---------------- w1p = w1 @ attW (fp32 SIMT, 4 rows per block) ---------------
__global__ void fold_w1_kernel(const float* __restrict__ w1, const float* __restrict__ attW,
                               float* __restrict__ w1p) {
    __shared__ float aw[64][65];
    __shared__ float wr[4][64];
    int tid = threadIdx.x;
    int row0 = blockIdx.x * 4;
    for (int t = tid; t < 4096; t += 256) aw[t >> 6][t & 63] = attW[t];
    {
        int r = tid >> 6, c = tid & 63;
        int gr = row0 + r;
        wr[r][c] = (gr < FIN) ? w1[(size_t)gr * 64 + c] : 0.0f;
    }
    __syncthreads();
    int r = tid >> 6, c = tid & 63;
    float acc = 0.0f;
    #pragma unroll
    for (int k = 0; k < 64; k++) acc += wr[r][k] * aw[k][c];
    int gr = row0 + r;
    if (gr < FIN) w1p[(size_t)gr * 64 + c] = acc;
}

// ---------------- weight hi/lo split (one launch, 8 segments, opt transpose) --
struct SplitArgs {
    const float* src[8];
    int n[8];
    int off[8];
    int tr[8];   // transpose 64x64
};
__global__ void split_kernel(SplitArgs a, float* __restrict__ hi, float* __restrict__ lo) {
    int seg = blockIdx.y;
    int i = blockIdx.x * 256 + threadIdx.x;
    if (i < a.n[seg]) {
        float x = a.tr[seg] ? a.src[seg][(i & 63) * 64 + (i >> 6)] : a.src[seg][i];
        float h = t32(x);
        hi[a.off[seg] + i] = h;
        lo[a.off[seg] + i] = t32(x - h);
    }
}

// ---------------- build sparse row lists (both matrices, one launch) ----------
__global__ void build_list_kernel(const float* __restrict__ matA, int* __restrict__ idxA,
                                  int* __restrict__ cntA,
                                  const float* __restrict__ matB, int* __restrict__ idxB,
                                  int* __restrict__ cntB) {
    int row = blockIdx.x;
    const float* mat = blockIdx.y ? matB : matA;
    int* idx = blockIdx.y ? idxB : idxA;
    int* cnt = blockIdx.y ? cntB : cntA;
    int tid = threadIdx.x;
    int wid = tid >> 5, lane = tid & 31;
    const float4* r4 = (const float4*)(mat + (size_t)row * NN);
    __shared__ int wsum[8];
    __shared__ int woff[8];
    float v[16];
    #pragma unroll
    for (int q = 0; q < 4; q++) {
        float4 x = r4[tid * 4 + q];
        v[q * 4 + 0] = x.x; v[q * 4 + 1] = x.y; v[q * 4 + 2] = x.z; v[q * 4 + 3] = x.w;
    }
    int base = tid * 16;
    int c = 0;
    #pragma unroll
    for (int j = 0; j < 16; j++) c += (v[j] != 0.0f);
    int inc = c;
    #pragma unroll
    for (int o = 1; o < 32; o <<= 1) {
        int t = __shfl_up_sync(FULLM, inc, o);
        if (lane >= o) inc += t;
    }
    if (lane == 31) wsum[wid] = inc;
    __syncthreads();
    if (tid < 8) {
        int t = wsum[tid];
        int iv = t;
        #pragma unroll
        for (int o = 1; o < 8; o <<= 1) {
            int u = __shfl_up_sync(0xffu, iv, o);
            if (tid >= o) iv += u;
        }
        woff[tid] = iv - t;
        if (tid == 7) cnt[row] = iv;
    }
    __syncthreads();
    int o = woff[wid] + inc - c;
    int* dst = idx + (size_t)row * MAXNNZ;
    #pragma unroll
    for (int j = 0; j < 16; j++) {
        if (v[j] != 0.0f) dst[o++] = base + j;
    }
}

// ---------------- tf32 WMMA GEMM (round-7 proven config) ----------------------
// C = act(A[M,K] @ B[K,N] + bias). BM=WARPS*16, BN=64, threads=WARPS*32.
// PREC=3: 3xtf32 compensated; PREC=1: plain tf32.
// split-K via blockIdx.z: kz = bz % kspl; bz >= kspl uses A2.
// act: 0 none, 1 relu, 2 raw->C + relu->C2, 3 raw->C only rows<NN + relu->C2.
template<int PREC, int WARPS, int BK>
__global__ __launch_bounds__(WARPS * 32, (WARPS == 8) ? 2 : 4)
void gemm_tc(const float* __restrict__ A, const float* __restrict__ A2,
             const float* __restrict__ Bhi, const float* __restrict__ Blo,
             const float* __restrict__ bias, float* __restrict__ C,
             float* __restrict__ C2, int M, int N, int K,
             int kChunk, int kspl, long long partStride, int act) {
    constexpr int BM = WARPS * 16;
    constexpr int TPB = WARPS * 32;
    constexpr int CPT = BM * BK / TPB;
    constexpr int AFR = CPT / 4;
    constexpr int BROWS = TPB / 16;
    constexpr int BITER = BK / BROWS;
    constexpr int LDA = BK + 4;

    int bz = blockIdx.z;
    int kz = bz % kspl;
    const float* Asrc = (bz < kspl) ? A : A2;
    int k0 = kz * kChunk;
    int k1 = min(K, k0 + kChunk);
    float* Cp = C + (long long)bz * partStride;
    int row0 = blockIdx.y * BM;
    int col0 = blockIdx.x * 64;
    int tid = threadIdx.x;
    int wid = tid >> 5;
    int lane = tid & 31;

    __shared__ float Ah[BM][LDA];
    __shared__ float Al[PREC == 3 ? BM : 1][LDA];
    __shared__ float Bh[BK][72];
    __shared__ float Bl[PREC == 3 ? BK : 1][72];
    __shared__ float Cb[WARPS][256];

    wmma::fragment<wmma::accumulator, 16, 16, 8, float> acc[4];
    #pragma unroll
    for (int f = 0; f < 4; f++) wmma::fill_fragment(acc[f], 0.0f);

    int ar = tid >> 1;
    int acb = (tid & 1) * CPT;
    const float* Arow = Asrc + (size_t)(row0 + ar) * K;
    int bn = (tid & 15) * 4;
    int bkb = tid >> 4;
    int gnB = col0 + bn;

    float4 aR[AFR], bhR[BITER], blR[BITER];
    const float4 f4z = make_float4(0.f, 0.f, 0.f, 0.f);

    auto loadTiles = [&](int kk) {
        #pragma unroll
        for (int v = 0; v < AFR; v++) {
            int gk = kk + acb + v * 4;
            aR[v] = (gk < k1) ? *(const float4*)(Arow + gk) : f4z;
        }
        #pragma unroll
        for (int i = 0; i < BITER; i++) {
            int gkb = kk + bkb + i * BROWS;
            bhR[i] = f4z;
            if (PREC == 3) blR[i] = f4z;
            if (gkb < k1 && gnB < N) {
                bhR[i] = *(const float4*)(Bhi + (size_t)gkb * N + gnB);
                if (PREC == 3) blR[i] = *(const float4*)(Blo + (size_t)gkb * N + gnB);
            }
        }
    };
    auto storeTiles = [&]() {
        #pragma unroll
        for (int v = 0; v < AFR; v++) {
            int c = acb + v * 4;
            float* dh = &Ah[ar][c];
            float* dl = &Al[PREC == 3 ? ar : 0][c];
            float h;
            h = t32(aR[v].x); dh[0] = h; if (PREC == 3) dl[0] = t32(aR[v].x - h);
            h = t32(aR[v].y); dh[1] = h; if (PREC == 3) dl[1] = t32(aR[v].y - h);
            h = t32(aR[v].z); dh[2] = h; if (PREC == 3) dl[2] = t32(aR[v].z - h);
            h = t32(aR[v].w); dh[3] = h; if (PREC == 3) dl[3] = t32(aR[v].w - h);
        }
        #pragma unroll
        for (int i = 0; i < BITER; i++) {
            *(float4*)&Bh[bkb + i * BROWS][bn] = bhR[i];
            if (PREC == 3) *(float4*)&Bl[bkb + i * BROWS][bn] = blR[i];
        }
    };

    loadTiles(k0);
    for (int kk = k0; kk < k1; kk += BK) {
        storeTiles();
        __syncthreads();
        int nk = kk + BK;
        if (nk < k1) loadTiles(nk);
        #pragma unroll
        for (int ks = 0; ks < BK; ks += 8) {
            wmma::fragment<wmma::matrix_a, 16, 16, 8, wmma::precision::tf32, wmma::row_major> ah, al;
            wmma::load_matrix_sync(ah, &Ah[wid * 16][ks], LDA);
            if (PREC == 3) wmma::load_matrix_sync(al, &Al[wid * 16][ks], LDA);
            #pragma unroll
            for (int f = 0; f < 4; f++) {
                wmma::fragment<wmma::matrix_b, 16, 16, 8, wmma::precision::tf32, wmma::row_major> bh, bl;
                wmma::load_matrix_sync(bh, &Bh[ks][f * 16], 72);
                if (PREC == 3) {
                    wmma::load_matrix_sync(bl, &Bl[ks][f * 16], 72);
                    wmma::mma_sync(acc[f], ah, bl, acc[f]);
                    wmma::mma_sync(acc[f], al, bh, acc[f]);
                }
                wmma::mma_sync(acc[f], ah, bh, acc[f]);
            }
        }
        __syncthreads();
    }

    int r0 = row0 + wid * 16;
    #pragma unroll
    for (int f = 0; f < 4; f++) {
        int c0 = col0 + f * 16;
        __syncwarp();
        wmma::store_matrix_sync(&Cb[wid][0], acc[f], 16, wmma::mem_row_major);
        __syncwarp();
        for (int e = lane; e < 256; e += 32) {
            int rr = e >> 4, cc = e & 15;
            int c = c0 + cc;
            if (c < N) {
                float v = Cb[wid][e];
                if (bias) v += bias[c];
                int gr = r0 + rr;
                size_t oi = (size_t)gr * N + c;
                if (act == 0) {
                    Cp[oi] = v;
                } else if (act == 1) {
                    Cp[oi] = fmaxf(v, 0.0f);
                } else if (act == 2) {
                    Cp[oi] = v;
                    C2[oi] = fmaxf(v, 0.0f);
                } else {  // act == 3
                    if (gr < NN) Cp[oi] = v;
                    C2[oi] = fmaxf(v, 0.0f);
                }
            }
        }
    }
}

// ---------------- fused split-K reduce -> Wh, plus s/d row dots ---------------
// block = 256 threads = 4 complete rows of 64. grid = 2*NN*64/256.
__global__ void reduce_sd_kernel(const float* __restrict__ part,
                                 const float* __restrict__ a_src,
                                 const float* __restrict__ a_dst,
                                 float* __restrict__ Wh, float* __restrict__ s,
                                 float* __restrict__ d) {
    const int HALF = NN * FOUT;
    int i = blockIdx.x * 256 + threadIdx.x;
    int h = i >= HALF;
    int j = i - h * HALF;
    const float* base = part + (size_t)h * KSPL * HALF;
    float v = 0.0f;
    #pragma unroll
    for (int z = 0; z < KSPL; z++) v += base[(size_t)z * HALF + j];
    Wh[i] = v;
    int col = i & 63;
    float vs = v * a_src[col];
    float vd = v * a_dst[col];
    #pragma unroll
    for (int o = 16; o > 0; o >>= 1) {
        vs += __shfl_down_sync(FULLM, vs, o);
        vd += __shfl_down_sync(FULLM, vd, o);
    }
    __shared__ float sh[2][8];
    int wid = threadIdx.x >> 5;
    if ((threadIdx.x & 31) == 0) { sh[0][wid] = vs; sh[1][wid] = vd; }
    __syncthreads();
    if ((threadIdx.x & 63) == 0) {
        int row = i >> 6;
        s[row] = sh[0][wid] + sh[0][wid + 1];
        d[row] = sh[1][wid] + sh[1][wid + 1];
    }
}

// ---------------- warp-per-row attention (online softmax), 8192 rows ----------
__global__ void att_warp_kernel(const int* __restrict__ idx, const int* __restrict__ cnt,
                                const float* __restrict__ s, const float* __restrict__ d,
                                const float* __restrict__ Wh, float* __restrict__ out) {
    int row = blockIdx.x * 8 + (threadIdx.x >> 5);
    int lane = threadIdx.x & 31;
    if (row >= 2 * NN) return;
    int grow = row & (NN - 1);
    int off = row & NN;
    int n = cnt[grow];
    const int* lst = idx + (size_t)grow * MAXNNZ;
    float si = s[row];
    float m = -3.4e38f, ssum = 0.0f, a0 = 0.0f, a1 = 0.0f;
    for (int base = 0; base < n; base += 32) {
        int t = base + lane;
        int j = 0;
        float e = -3.4e38f;
        if (t < n) {
            j = lst[t];
            float v = si + d[j + off];
            e = v > 0.0f ? v : 0.2f * v;
        }
        float cm = e;
        #pragma unroll
        for (int o = 16; o > 0; o >>= 1) cm = fmaxf(cm, __shfl_xor_sync(FULLM, cm, o));
        float nm = fmaxf(m, cm);
        float scale = expf(m - nm);
        a0 *= scale; a1 *= scale; ssum *= scale;
        float w = (t < n) ? expf(e - nm) : 0.0f;
        float cs = w;
        #pragma unroll
        for (int o = 16; o > 0; o >>= 1) cs += __shfl_xor_sync(FULLM, cs, o);
        ssum += cs;
        int lim = min(32, n - base);
        for (int q = 0; q < lim; q++) {
            float wq = __shfl_sync(FULLM, w, q);
            int jq = __shfl_sync(FULLM, j, q);
            const float* r = Wh + (size_t)(jq + off) * 64;
            a0 += wq * r[lane];
            a1 += wq * r[lane + 32];
        }
        m = nm;
    }
    float inv = 1.0f / ssum;
    out[(size_t)row * 64 + lane] = a0 * inv;
    out[(size_t)row * 64 + lane + 32] = a1 * inv;
}

// ---------------- adjz = adj @ z (warp per row; z lives in d_out) -------------
__global__ void agg_warp_kernel(const int* __restrict__ idx, const int* __restrict__ cnt,
                                const float* __restrict__ z, float* __restrict__ out) {
    int row = blockIdx.x * 8 + (threadIdx.x >> 5);
    int lane = threadIdx.x & 31;
    if (row >= NN) return;
    int n = cnt[row];
    const int* lst = idx + (size_t)row * MAXNNZ;
    float a0 = 0.0f, a1 = 0.0f;
    for (int base = 0; base < n; base += 32) {
        int t = base + lane;
        int j = (t < n) ? lst[t] : 0;
        int lim = min(32, n - base);
        for (int q = 0; q < lim; q++) {
            int jq = __shfl_sync(FULLM, j, q);
            const float* r = z + (size_t)jq * 64;
            a0 += r[lane];
            a1 += r[lane + 32];
        }
    }
    out[(size_t)row * 64 + lane] = a0;
    out[(size_t)row * 64 + lane + 32] = a1;
}

// ---------------- warp-per-row readout: mean, L2-norm, sigmoid (8192 rows) ----
__global__ void readout_warp_kernel(const int* __restrict__ idx, const int* __restrict__ cnt,
                                    float* __restrict__ dcat) {
    int row = blockIdx.x * 8 + (threadIdx.x >> 5);
    int lane = threadIdx.x & 31;
    if (row >= 2 * NN) return;
    int grow = row & (NN - 1);
    int n = cnt[grow];
    const int* lst = idx + (size_t)grow * MAXNNZ;
    int off = (row < NN) ? 2 * NN : 3 * NN;
    float a0 = 0.0f, a1 = 0.0f;
    for (int base = 0; base < n; base += 32) {
        int t = base + lane;
        int j = (t < n) ? lst[t] : 0;
        int lim = min(32, n - base);
        for (int q = 0; q < lim; q++) {
            int jq = __shfl_sync(FULLM, j, q);
            const float* r = dcat + (size_t)(off + jq) * 64;
            a0 += r[lane];
            a1 += r[lane + 32];
        }
    }
    float invn = 1.0f / (float)n;
    float v0 = a0 * invn, v1 = a1 * invn;
    float ss = v0 * v0 + v1 * v1;
    #pragma unroll
    for (int o = 16; o > 0; o >>= 1) ss += __shfl_xor_sync(FULLM, ss, o);
    float den = fmaxf(sqrtf(ss), 1e-12f);
    float x0 = v0 / den, x1 = v1 / den;
    dcat[(size_t)row * 64 + lane] = 1.0f / (1.0f + expf(-x0));
    dcat[(size_t)row * 64 + lane + 32] = 1.0f / (1.0f + expf(-x1));
}

// ---------------- bilinear outputs (warp per logical row, 8192 rows) ----------
__global__ void bilin_warp_kernel(const float* __restrict__ qcat, const float* __restrict__ u,
                                  const float* __restrict__ b, float* __restrict__ ret,
                                  float* __restrict__ reta) {
    int row = blockIdx.x * 8 + (threadIdx.x >> 5);
    int lane = threadIdx.x & 31;
    if (row >= 2 * NN) return;
    int r = row & (NN - 1);
    const float* ur = u + (size_t)row * 64;
    const float* xpl = qcat + (size_t)(2 * NN + r) * 64;
    const float* xmi = qcat + (size_t)(3 * NN + r) * 64;
    float v0, v1;
    if (row < NN) {
        v0 = xpl[lane] * ur[lane] + xpl[lane + 32] * ur[lane + 32];
        v1 = xmi[lane] * ur[lane] + xmi[lane + 32] * ur[lane + 32];
    } else {
        v0 = xmi[lane] * ur[lane] + xmi[lane + 32] * ur[lane + 32];
        v1 = xpl[lane] * ur[lane] + xpl[lane + 32] * ur[lane + 32];
    }
    #pragma unroll
    for (int o = 16; o > 0; o >>= 1) {
        v0 += __shfl_down_sync(FULLM, v0, o);
        v1 += __shfl_down_sync(FULLM, v1, o);
    }
    if (lane == 0) {
        float* dst = (row < NN) ? ret : reta;
        dst[(size_t)r * 2 + 0] = v0 + b[0];
        dst[(size_t)r * 2 + 1] = v1 + b[0];
    }
}

// ---------------- host ----------------
static void* sym(const void* s) {
    void* p = nullptr;
    cudaGetSymbolAddress(&p, s);
    return p;
}

extern "C" void kernel_launch(void* const* d_in, const int* in_sizes, int n_in,
                              void* d_out, int out_size) {
    const float* feat   = (const float*)d_in[0];
    const float* feat_a = (const float*)d_in[1];
    const float* adj    = (const float*)d_in[2];
    const float* gn     = (const float*)d_in[3];
    const float* w1     = (const float*)d_in[4];
    const float* w2     = (const float*)d_in[5];
    const float* attW   = (const float*)d_in[6];
    const float* a_src  = (const float*)d_in[7];
    const float* a_dst  = (const float*)d_in[8];
    const float* mW1 = (const float*)d_in[9];  const float* mb1 = (const float*)d_in[10];
    const float* mW2 = (const float*)d_in[11]; const float* mb2 = (const float*)d_in[12];
    const float* mW3 = (const float*)d_in[13]; const float* mb3 = (const float*)d_in[14];
    const float* dW1 = (const float*)d_in[15]; const float* db1 = (const float*)d_in[16];
    const float* dW2 = (const float*)d_in[17]; const float* db2 = (const float*)d_in[18];
    const float* bilW = (const float*)d_in[19];
    const float* bilb = (const float*)d_in[20];

    float* out      = (float*)d_out;
    float* out_h    = out + (size_t)NN * FOUT;
    float* out_ret  = out_h + (size_t)NN * FIN;
    float* out_reta = out_ret + (size_t)NN * 2;

    float* w1p  = (float*)sym(g_w1p);
    float* Wh   = (float*)sym(g_Wh);
    float* sv   = (float*)sym(g_s);
    float* dv   = (float*)sym(g_d);
    float* att  = (float*)sym(g_att);
    float* t1   = (float*)sym(g_t1);
    float* t2   = (float*)sym(g_t2);
    float* adjz = (float*)sym(g_adjz);
    float* dcat = (float*)sym(g_dcat);
    float* dh   = (float*)sym(g_dh);
    float* qcat = (float*)sym(g_qcat);
    float* u    = (float*)sym(g_u);
    float* part = (float*)sym(g_part);
    float* Bhi  = (float*)sym(g_Bhi);
    float* Blo  = (float*)sym(g_Blo);
    int* aidx = (int*)sym(g_adj_idx); int* acnt = (int*)sym(g_adj_cnt);
    int* gidx = (int*)sym(g_gn_idx);  int* gcnt = (int*)sym(g_gn_cnt);

    const int M2 = 2 * NN;   // 8192
    const int M4 = 4 * NN;   // 16384
    const long long PS = (long long)NN * FOUT;

    // 1. sparse lists + w1p = w1 @ attW + weight split (bilW transposed in split)
    build_list_kernel<<<dim3(NN, 2), 256>>>(adj, aidx, acnt, gn, gidx, gcnt);
    fold_w1_kernel<<<(FIN + 3) / 4, 256>>>(w1, attW, w1p);
    {
        SplitArgs sa;
        sa.src[0] = w1p;  sa.n[0] = FIN * FOUT;  sa.off[0] = OFF_W1;  sa.tr[0] = 0;
        sa.src[1] = w2;   sa.n[1] = FOUT * FIN;  sa.off[1] = OFF_W2;  sa.tr[1] = 0;
        sa.src[2] = mW1;  sa.n[2] = 64 * 256;    sa.off[2] = OFF_MW1; sa.tr[2] = 0;
        sa.src[3] = mW2;  sa.n[3] = 256 * 128;   sa.off[3] = OFF_MW2; sa.tr[3] = 0;
        sa.src[4] = mW3;  sa.n[4] = 128 * 64;    sa.off[4] = OFF_MW3; sa.tr[4] = 0;
        sa.src[5] = dW1;  sa.n[5] = 64 * 128;    sa.off[5] = OFF_DW1; sa.tr[5] = 0;
        sa.src[6] = dW2;  sa.n[6] = 128 * 64;    sa.off[6] = OFF_DW2; sa.tr[6] = 0;
        sa.src[7] = bilW; sa.n[7] = 64 * 64;     sa.off[7] = OFF_WT;  sa.tr[7] = 1;
        split_kernel<<<dim3((FIN * FOUT + 255) / 256, 8), 256>>>(sa, Bhi, Blo);
    }

    // 2. part = [feat; feat_a] @ w1p  (plain tf32, split-K=9 -> 576 CTAs)
    gemm_tc<1, 8, 32><<<dim3(1, NN / 128, 2 * KSPL), 256>>>(
        feat, feat_a, Bhi + OFF_W1, Blo + OFF_W1, nullptr, part, nullptr,
        NN, FOUT, FIN, 336, KSPL, PS, 0);
    // fused reduce -> Wh (2NN x 64) + s/d row dots
    reduce_sd_kernel<<<(M2 * FOUT) / 256, 256>>>(part, a_src, a_dst, Wh, sv, dv);

    // 3. attention + MLP over 8192 rows (3xtf32)
    att_warp_kernel<<<M2 / 8, 256>>>(aidx, acnt, sv, dv, Wh, att);
    gemm_tc<3, 4, 16><<<dim3(4, M2 / 64, 1), 128>>>(att, nullptr, Bhi + OFF_MW1, Blo + OFF_MW1,
                                                    mb1, t1, nullptr, M2, 256, 64, 64, 1, 0, 1);
    gemm_tc<3, 4, 16><<<dim3(2, M2 / 64, 1), 128>>>(t1, nullptr, Bhi + OFF_MW2, Blo + OFF_MW2,
                                                    mb2, t2, nullptr, M2, 128, 256, 256, 1, 0, 1);
    // MLP3: raw -> out (rows < NN = hiden_emb/z), relu -> dcat[8192..16383] (emb; emba)
    gemm_tc<3, 4, 16><<<dim3(1, M2 / 64, 1), 128>>>(t2, nullptr, Bhi + OFF_MW3, Blo + OFF_MW3,
                                                    mb3, out, dcat + (size_t)M2 * FOUT,
                                                    M2, 64, 128, 128, 1, 0, 3);

    // 4. h = (adj @ z) @ w2  (z read from d_out; plain tf32)
    agg_warp_kernel<<<NN / 8, 256>>>(aidx, acnt, out, adjz);
    gemm_tc<1, 8, 32><<<dim3((FIN + 63) / 64, NN / 128, 1), 256>>>(
        adjz, nullptr, Bhi + OFF_W2, Blo + OFF_W2, nullptr, out_h, nullptr,
        NN, FIN, FOUT, FOUT, 1, 0, 0);

    // 5. readouts -> dcat[0..8191] = [gv; gva]
    readout_warp_kernel<<<M2 / 8, 256>>>(gidx, gcnt, dcat);

    // 6. discriminator MLP over all 16384 rows -> qcat = [dc; dca; dpl; dmi]
    gemm_tc<3, 4, 16><<<dim3(2, M4 / 64, 1), 128>>>(dcat, nullptr, Bhi + OFF_DW1, Blo + OFF_DW1,
                                                    db1, dh, nullptr, M4, 128, 64, 64, 1, 0, 1);
    gemm_tc<3, 4, 16><<<dim3(1, M4 / 64, 1), 128>>>(dh, nullptr, Bhi + OFF_DW2, Blo + OFF_DW2,
                                                    db2, qcat, nullptr, M4, 64, 128, 128, 1, 0, 0);

    // 7. bilinear
    gemm_tc<3, 4, 16><<<dim3(1, M2 / 64, 1), 128>>>(qcat, nullptr, Bhi + OFF_WT, Blo + OFF_WT,
                                                    nullptr, u, nullptr, M2, 64, 64, 64, 1, 0, 0);
    bilin_warp_kernel<<<M2 / 8, 256>>>(qcat, u, bilb, out_ret, out_reta);
}

// round 13
// speedup vs baseline: 1.2650x; 1.0623x over previous
#include <cuda_runtime.h>
#include <stdint.h>
#include <math.h>
#include <mma.h>

using namespace nvcuda;

#define NN 4096
#define FIN 3000
#define FOUT 64
#define MAXNNZ 512
#define KSPL 6
#define FULLM 0xffffffffu

// ---------------- scratch (static device memory; no allocation) ----------------
__device__ float g_w1p [FIN*FOUT];       // w1 @ attW
__device__ float g_Wh  [2*NN*FOUT];
__device__ float g_s   [2*NN];
__device__ float g_d   [2*NN];
__device__ float g_att [2*NN*FOUT];
__device__ float g_t1  [2*NN*256];
__device__ float g_t2  [2*NN*128];
__device__ float g_adjz[NN*FOUT];
__device__ float g_dcat[4*NN*FOUT];      // [gv; gva; emb; emba]
__device__ float g_dh  [4*NN*128];
__device__ float g_qcat[4*NN*FOUT];      // [dc; dca; dpl; dmi]
__device__ float g_u   [2*NN*FOUT];      // [u; ua]
__device__ float g_part[2*KSPL*NN*FOUT];
__device__ int   g_adj_idx[NN*MAXNNZ];
__device__ int   g_adj_cnt[NN];
__device__ int   g_gn_idx [NN*MAXNNZ];
__device__ int   g_gn_cnt [NN];

// precomputed tf32 hi/lo weight buffers (concatenated)
#define OFF_W1   0
#define OFF_W2   192000
#define OFF_MW1  384000
#define OFF_MW2  400384
#define OFF_MW3  433152
#define OFF_DW1  441344
#define OFF_DW2  449536
#define OFF_WT   457728
#define SPLIT_TOTAL 461824
__device__ float g_Bhi[SPLIT_TOTAL];
__device__ float g_Blo[SPLIT_TOTAL];

__device__ __forceinline__ float t32(float x) { return wmma::__float_to_tf32(x); }

__device__ __forceinline__ uint32_t s2u(const void* p) {
    return (uint32_t)__cvta_generic_to_shared(p);
}
__device__ __forceinline__ void cpa16(uint32_t dst, const void* src, int bytes) {
    asm volatile("cp.async.cg.shared.global [%0], [%1], 16, %2;"
                 :: "r"(dst), "l"(src), "r"(bytes));
}

// ---------------- w1p = w1 @ attW (fp32 SIMT, 4 rows per block) ---------------
__global__ void fold_w1_kernel(const float* __restrict__ w1, const float* __restrict__ attW,
                               float* __restrict__ w1p) {
    __shared__ float aw[64][65];
    __shared__ float wr[4][64];
    int tid = threadIdx.x;
    int row0 = blockIdx.x * 4;
    for (int t = tid; t < 4096; t += 256) aw[t >> 6][t & 63] = attW[t];
    {
        int r = tid >> 6, c = tid & 63;
        int gr = row0 + r;
        wr[r][c] = (gr < FIN) ? w1[(size_t)gr * 64 + c] : 0.0f;
    }
    __syncthreads();
    int r = tid >> 6, c = tid & 63;
    float acc = 0.0f;
    #pragma unroll
    for (int k = 0; k < 64; k++) acc += wr[r][k] * aw[k][c];
    int gr = row0 + r;
    if (gr < FIN) w1p[(size_t)gr * 64 + c] = acc;
}

// ---------------- weight hi/lo split (one launch, 8 segments, opt transpose) --
struct SplitArgs {
    const float* src[8];
    int n[8];
    int off[8];
    int tr[8];   // transpose 64x64
};
__global__ void split_kernel(SplitArgs a, float* __restrict__ hi, float* __restrict__ lo) {
    int seg = blockIdx.y;
    int i = blockIdx.x * 256 + threadIdx.x;
    if (i < a.n[seg]) {
        float x = a.tr[seg] ? a.src[seg][(i & 63) * 64 + (i >> 6)] : a.src[seg][i];
        float h = t32(x);
        hi[a.off[seg] + i] = h;
        lo[a.off[seg] + i] = t32(x - h);
    }
}

// ---------------- build sparse row lists (both matrices, one launch) ----------
__global__ void build_list_kernel(const float* __restrict__ matA, int* __restrict__ idxA,
                                  int* __restrict__ cntA,
                                  const float* __restrict__ matB, int* __restrict__ idxB,
                                  int* __restrict__ cntB) {
    int row = blockIdx.x;
    const float* mat = blockIdx.y ? matB : matA;
    int* idx = blockIdx.y ? idxB : idxA;
    int* cnt = blockIdx.y ? cntB : cntA;
    int tid = threadIdx.x;
    int wid = tid >> 5, lane = tid & 31;
    const float4* r4 = (const float4*)(mat + (size_t)row * NN);
    __shared__ int wsum[8];
    __shared__ int woff[8];
    float v[16];
    #pragma unroll
    for (int q = 0; q < 4; q++) {
        float4 x = r4[tid * 4 + q];
        v[q * 4 + 0] = x.x; v[q * 4 + 1] = x.y; v[q * 4 + 2] = x.z; v[q * 4 + 3] = x.w;
    }
    int base = tid * 16;
    int c = 0;
    #pragma unroll
    for (int j = 0; j < 16; j++) c += (v[j] != 0.0f);
    int inc = c;
    #pragma unroll
    for (int o = 1; o < 32; o <<= 1) {
        int t = __shfl_up_sync(FULLM, inc, o);
        if (lane >= o) inc += t;
    }
    if (lane == 31) wsum[wid] = inc;
    __syncthreads();
    if (tid < 8) {
        int t = wsum[tid];
        int iv = t;
        #pragma unroll
        for (int o = 1; o < 8; o <<= 1) {
            int u = __shfl_up_sync(0xffu, iv, o);
            if (tid >= o) iv += u;
        }
        woff[tid] = iv - t;
        if (tid == 7) cnt[row] = iv;
    }
    __syncthreads();
    int o = woff[wid] + inc - c;
    int* dst = idx + (size_t)row * MAXNNZ;
    #pragma unroll
    for (int j = 0; j < 16; j++) {
        if (v[j] != 0.0f) dst[o++] = base + j;
    }
}

// ---------------- plain-tf32 GEMM, cp.async double-buffered -------------------
// C = A[M,K] @ B[K,N] (no bias/act). BM=128, BN=64, BK=16, 256 threads.
// A raw fp32 via cp.async; tf32 RN conversion applied on fragment registers.
// B = precomputed tf32 hi. split-K via blockIdx.z; bz >= kspl uses A2.
__global__ __launch_bounds__(256, 3)
void gemm_cp(const float* __restrict__ A, const float* __restrict__ A2,
             const float* __restrict__ Bhi, float* __restrict__ C,
             int M, int N, int K, int kChunk, int kspl, long long partStride) {
    constexpr int BK = 16;
    constexpr int LDA = 20;
    __shared__ float Ah[2][128][LDA];
    __shared__ float Bh[2][BK][72];
    __shared__ float Cb[8][256];

    int bz = blockIdx.z;
    int kz = bz % kspl;
    const float* Asrc = (bz < kspl) ? A : A2;
    int k0 = kz * kChunk;
    int k1 = min(K, k0 + kChunk);
    float* Cp = C + (long long)bz * partStride;
    int row0 = blockIdx.y * 128;
    int col0 = blockIdx.x * 64;
    int tid = threadIdx.x;
    int wid = tid >> 5;
    int lane = tid & 31;

    wmma::fragment<wmma::accumulator, 16, 16, 8, float> acc[4];
    #pragma unroll
    for (int f = 0; f < 4; f++) wmma::fill_fragment(acc[f], 0.0f);

    auto loadTiles = [&](int buf, int kk) {
        // A tile: 128 x 16 floats = 512 16B chunks; 2 per thread
        #pragma unroll
        for (int v = 0; v < 2; v++) {
            int id = tid + v * 256;
            int row = id >> 2, c4 = id & 3;
            int gk = kk + c4 * 4;
            int bytes = (k1 - gk) * 4;
            bytes = bytes < 0 ? 0 : (bytes > 16 ? 16 : bytes);
            const float* src = Asrc + (size_t)(row0 + row) * K + (bytes > 0 ? gk : k0);
            cpa16(s2u(&Ah[buf][row][c4 * 4]), src, bytes);
        }
        // B tile: 16 x 64 floats = 256 chunks; 1 per thread
        {
            int row = tid >> 4, c4 = tid & 15;
            int gk = kk + row;
            int gn = col0 + c4 * 4;
            int bytes = 0;
            if (gk < k1) {
                bytes = (N - gn) * 4;
                bytes = bytes < 0 ? 0 : (bytes > 16 ? 16 : bytes);
            }
            const float* src = Bhi + (size_t)(bytes > 0 ? gk : k0) * N
                                   + (bytes > 0 ? gn : col0);
            cpa16(s2u(&Bh[buf][row][c4 * 4]), src, bytes);
        }
        asm volatile("cp.async.commit_group;");
    };

    int nIter = (k1 - k0 + BK - 1) / BK;
    loadTiles(0, k0);
    for (int it = 0; it < nIter; it++) {
        if (it + 1 < nIter) {
            loadTiles((it + 1) & 1, k0 + (it + 1) * BK);
            asm volatile("cp.async.wait_group 1;");
        } else {
            asm volatile("cp.async.wait_group 0;");
        }
        __syncthreads();
        int buf = it & 1;
        #pragma unroll
        for (int ks = 0; ks < BK; ks += 8) {
            wmma::fragment<wmma::matrix_a, 16, 16, 8, wmma::precision::tf32, wmma::row_major> ah;
            wmma::load_matrix_sync(ah, &Ah[buf][wid * 16][ks], LDA);
            #pragma unroll
            for (int i = 0; i < ah.num_elements; i++) ah.x[i] = t32(ah.x[i]);
            #pragma unroll
            for (int f = 0; f < 4; f++) {
                wmma::fragment<wmma::matrix_b, 16, 16, 8, wmma::precision::tf32, wmma::row_major> bh;
                wmma::load_matrix_sync(bh, &Bh[buf][ks][f * 16], 72);
                wmma::mma_sync(acc[f], ah, bh, acc[f]);
            }
        }
        __syncthreads();
    }

    int r0 = row0 + wid * 16;
    #pragma unroll
    for (int f = 0; f < 4; f++) {
        int c0 = col0 + f * 16;
        __syncwarp();
        wmma::store_matrix_sync(&Cb[wid][0], acc[f], 16, wmma::mem_row_major);
        __syncwarp();
        for (int e = lane; e < 256; e += 32) {
            int rr = e >> 4, cc = e & 15;
            int c = c0 + cc;
            if (c < N) Cp[(size_t)(r0 + rr) * N + c] = Cb[wid][e];
        }
    }
}

// ---------------- 3xtf32 WMMA GEMM (proven small-GEMM config) -----------------
// C = act(A[M,K] @ B[K,N] + bias). BM=WARPS*16, BN=64, threads=WARPS*32.
// act: 0 none, 1 relu, 2 raw->C + relu->C2, 3 raw->C only rows<NN + relu->C2.
template<int WARPS, int BK>
__global__ __launch_bounds__(WARPS * 32, 4)
void gemm_tc3(const float* __restrict__ A,
              const float* __restrict__ Bhi, const float* __restrict__ Blo,
              const float* __restrict__ bias, float* __restrict__ C,
              float* __restrict__ C2, int M, int N, int K, int act) {
    constexpr int BM = WARPS * 16;
    constexpr int TPB = WARPS * 32;
    constexpr int CPT = BM * BK / TPB;
    constexpr int AFR = CPT / 4;
    constexpr int BROWS = TPB / 16;
    constexpr int BITER = BK / BROWS;
    constexpr int LDA = BK + 4;

    int row0 = blockIdx.y * BM;
    int col0 = blockIdx.x * 64;
    int tid = threadIdx.x;
    int wid = tid >> 5;
    int lane = tid & 31;

    __shared__ float Ah[BM][LDA];
    __shared__ float Al[BM][LDA];
    __shared__ float Bh[BK][72];
    __shared__ float Bl[BK][72];
    __shared__ float Cb[WARPS][256];

    wmma::fragment<wmma::accumulator, 16, 16, 8, float> acc[4];
    #pragma unroll
    for (int f = 0; f < 4; f++) wmma::fill_fragment(acc[f], 0.0f);

    int ar = tid >> 1;
    int acb = (tid & 1) * CPT;
    const float* Arow = A + (size_t)(row0 + ar) * K;
    int bn = (tid & 15) * 4;
    int bkb = tid >> 4;
    int gnB = col0 + bn;

    float4 aR[AFR], bhR[BITER], blR[BITER];
    const float4 f4z = make_float4(0.f, 0.f, 0.f, 0.f);

    auto loadTiles = [&](int kk) {
        #pragma unroll
        for (int v = 0; v < AFR; v++) {
            int gk = kk + acb + v * 4;
            aR[v] = (gk < K) ? *(const float4*)(Arow + gk) : f4z;
        }
        #pragma unroll
        for (int i = 0; i < BITER; i++) {
            int gkb = kk + bkb + i * BROWS;
            bhR[i] = f4z;
            blR[i] = f4z;
            if (gkb < K && gnB < N) {
                bhR[i] = *(const float4*)(Bhi + (size_t)gkb * N + gnB);
                blR[i] = *(const float4*)(Blo + (size_t)gkb * N + gnB);
            }
        }
    };
    auto storeTiles = [&]() {
        #pragma unroll
        for (int v = 0; v < AFR; v++) {
            int c = acb + v * 4;
            float* dh = &Ah[ar][c];
            float* dl = &Al[ar][c];
            float h;
            h = t32(aR[v].x); dh[0] = h; dl[0] = t32(aR[v].x - h);
            h = t32(aR[v].y); dh[1] = h; dl[1] = t32(aR[v].y - h);
            h = t32(aR[v].z); dh[2] = h; dl[2] = t32(aR[v].z - h);
            h = t32(aR[v].w); dh[3] = h; dl[3] = t32(aR[v].w - h);
        }
        #pragma unroll
        for (int i = 0; i < BITER; i++) {
            *(float4*)&Bh[bkb + i * BROWS][bn] = bhR[i];
            *(float4*)&Bl[bkb + i * BROWS][bn] = blR[i];
        }
    };

    loadTiles(0);
    for (int kk = 0; kk < K; kk += BK) {
        storeTiles();
        __syncthreads();
        int nk = kk + BK;
        if (nk < K) loadTiles(nk);
        #pragma unroll
        for (int ks = 0; ks < BK; ks += 8) {
            wmma::fragment<wmma::matrix_a, 16, 16, 8, wmma::precision::tf32, wmma::row_major> ah, al;
            wmma::load_matrix_sync(ah, &Ah[wid * 16][ks], LDA);
            wmma::load_matrix_sync(al, &Al[wid * 16][ks], LDA);
            #pragma unroll
            for (int f = 0; f < 4; f++) {
                wmma::fragment<wmma::matrix_b, 16, 16, 8, wmma::precision::tf32, wmma::row_major> bh, bl;
                wmma::load_matrix_sync(bh, &Bh[ks][f * 16], 72);
                wmma::load_matrix_sync(bl, &Bl[ks][f * 16], 72);
                wmma::mma_sync(acc[f], ah, bl, acc[f]);
                wmma::mma_sync(acc[f], al, bh, acc[f]);
                wmma::mma_sync(acc[f], ah, bh, acc[f]);
            }
        }
        __syncthreads();
    }

    int r0 = row0 + wid * 16;
    #pragma unroll
    for (int f = 0; f < 4; f++) {
        int c0 = col0 + f * 16;
        __syncwarp();
        wmma::store_matrix_sync(&Cb[wid][0], acc[f], 16, wmma::mem_row_major);
        __syncwarp();
        for (int e = lane; e < 256; e += 32) {
            int rr = e >> 4, cc = e & 15;
            int c = c0 + cc;
            if (c < N) {
                float v = Cb[wid][e];
                if (bias) v += bias[c];
                int gr = r0 + rr;
                size_t oi = (size_t)gr * N + c;
                if (act == 0) {
                    C[oi] = v;
                } else if (act == 1) {
                    C[oi] = fmaxf(v, 0.0f);
                } else if (act == 2) {
                    C[oi] = v;
                    C2[oi] = fmaxf(v, 0.0f);
                } else {  // act == 3
                    if (gr < NN) C[oi] = v;
                    C2[oi] = fmaxf(v, 0.0f);
                }
            }
        }
    }
}

// ---------------- fused split-K reduce -> Wh, plus s/d row dots ---------------
__global__ void reduce_sd_kernel(const float* __restrict__ part,
                                 const float* __restrict__ a_src,
                                 const float* __restrict__ a_dst,
                                 float* __restrict__ Wh, float* __restrict__ s,
                                 float* __restrict__ d) {
    const int HALF = NN * FOUT;
    int i = blockIdx.x * 256 + threadIdx.x;
    int h = i >= HALF;
    int j = i - h * HALF;
    const float* base = part + (size_t)h * KSPL * HALF;
    float v = 0.0f;
    #pragma unroll
    for (int z = 0; z < KSPL; z++) v += base[(size_t)z * HALF + j];
    Wh[i] = v;
    int col = i & 63;
    float vs = v * a_src[col];
    float vd = v * a_dst[col];
    #pragma unroll
    for (int o = 16; o > 0; o >>= 1) {
        vs += __shfl_down_sync(FULLM, vs, o);
        vd += __shfl_down_sync(FULLM, vd, o);
    }
    __shared__ float sh[2][8];
    int wid = threadIdx.x >> 5;
    if ((threadIdx.x & 31) == 0) { sh[0][wid] = vs; sh[1][wid] = vd; }
    __syncthreads();
    if ((threadIdx.x & 63) == 0) {
        int row = i >> 6;
        s[row] = sh[0][wid] + sh[0][wid + 1];
        d[row] = sh[1][wid] + sh[1][wid + 1];
    }
}

// ---------------- warp-per-row attention (online softmax), 8192 rows ----------
__global__ void att_warp_kernel(const int* __restrict__ idx, const int* __restrict__ cnt,
                                const float* __restrict__ s, const float* __restrict__ d,
                                const float* __restrict__ Wh, float* __restrict__ out) {
    int row = blockIdx.x * 8 + (threadIdx.x >> 5);
    int lane = threadIdx.x & 31;
    if (row >= 2 * NN) return;
    int grow = row & (NN - 1);
    int off = row & NN;
    int n = cnt[grow];
    const int* lst = idx + (size_t)grow * MAXNNZ;
    float si = s[row];
    float m = -3.4e38f, ssum = 0.0f, a0 = 0.0f, a1 = 0.0f;
    for (int base = 0; base < n; base += 32) {
        int t = base + lane;
        int j = 0;
        float e = -3.4e38f;
        if (t < n) {
            j = lst[t];
            float v = si + d[j + off];
            e = v > 0.0f ? v : 0.2f * v;
        }
        float cm = e;
        #pragma unroll
        for (int o = 16; o > 0; o >>= 1) cm = fmaxf(cm, __shfl_xor_sync(FULLM, cm, o));
        float nm = fmaxf(m, cm);
        float scale = expf(m - nm);
        a0 *= scale; a1 *= scale; ssum *= scale;
        float w = (t < n) ? expf(e - nm) : 0.0f;
        float cs = w;
        #pragma unroll
        for (int o = 16; o > 0; o >>= 1) cs += __shfl_xor_sync(FULLM, cs, o);
        ssum += cs;
        int lim = min(32, n - base);
        for (int q = 0; q < lim; q++) {
            float wq = __shfl_sync(FULLM, w, q);
            int jq = __shfl_sync(FULLM, j, q);
            const float* r = Wh + (size_t)(jq + off) * 64;
            a0 += wq * r[lane];
            a1 += wq * r[lane + 32];
        }
        m = nm;
    }
    float inv = 1.0f / ssum;
    out[(size_t)row * 64 + lane] = a0 * inv;
    out[(size_t)row * 64 + lane + 32] = a1 * inv;
}

// ---------------- adjz = adj @ z (warp per row; z lives in d_out) -------------
__global__ void agg_warp_kernel(const int* __restrict__ idx, const int* __restrict__ cnt,
                                const float* __restrict__ z, float* __restrict__ out) {
    int row = blockIdx.x * 8 + (threadIdx.x >> 5);
    int lane = threadIdx.x & 31;
    if (row >= NN) return;
    int n = cnt[row];
    const int* lst = idx + (size_t)row * MAXNNZ;
    float a0 = 0.0f, a1 = 0.0f;
    for (int base = 0; base < n; base += 32) {
        int t = base + lane;
        int j = (t < n) ? lst[t] : 0;
        int lim = min(32, n - base);
        for (int q = 0; q < lim; q++) {
            int jq = __shfl_sync(FULLM, j, q);
            const float* r = z + (size_t)jq * 64;
            a0 += r[lane];
            a1 += r[lane + 32];
        }
    }
    out[(size_t)row * 64 + lane] = a0;
    out[(size_t)row * 64 + lane + 32] = a1;
}

// ---------------- warp-per-row readout: mean, L2-norm, sigmoid (8192 rows) ----
__global__ void readout_warp_kernel(const int* __restrict__ idx, const int* __restrict__ cnt,
                                    float* __restrict__ dcat) {
    int row = blockIdx.x * 8 + (threadIdx.x >> 5);
    int lane = threadIdx.x & 31;
    if (row >= 2 * NN) return;
    int grow = row & (NN - 1);
    int n = cnt[grow];
    const int* lst = idx + (size_t)grow * MAXNNZ;
    int off = (row < NN) ? 2 * NN : 3 * NN;
    float a0 = 0.0f, a1 = 0.0f;
    for (int base = 0; base < n; base += 32) {
        int t = base + lane;
        int j = (t < n) ? lst[t] : 0;
        int lim = min(32, n - base);
        for (int q = 0; q < lim; q++) {
            int jq = __shfl_sync(FULLM, j, q);
            const float* r = dcat + (size_t)(off + jq) * 64;
            a0 += r[lane];
            a1 += r[lane + 32];
        }
    }
    float invn = 1.0f / (float)n;
    float v0 = a0 * invn, v1 = a1 * invn;
    float ss = v0 * v0 + v1 * v1;
    #pragma unroll
    for (int o = 16; o > 0; o >>= 1) ss += __shfl_xor_sync(FULLM, ss, o);
    float den = fmaxf(sqrtf(ss), 1e-12f);
    float x0 = v0 / den, x1 = v1 / den;
    dcat[(size_t)row * 64 + lane] = 1.0f / (1.0f + expf(-x0));
    dcat[(size_t)row * 64 + lane + 32] = 1.0f / (1.0f + expf(-x1));
}

// ---------------- bilinear outputs (warp per logical row, 8192 rows) ----------
__global__ void bilin_warp_kernel(const float* __restrict__ qcat, const float* __restrict__ u,
                                  const float* __restrict__ b, float* __restrict__ ret,
                                  float* __restrict__ reta) {
    int row = blockIdx.x * 8 + (threadIdx.x >> 5);
    int lane = threadIdx.x & 31;
    if (row >= 2 * NN) return;
    int r = row & (NN - 1);
    const float* ur = u + (size_t)row * 64;
    const float* xpl = qcat + (size_t)(2 * NN + r) * 64;
    const float* xmi = qcat + (size_t)(3 * NN + r) * 64;
    float v0, v1;
    if (row < NN) {
        v0 = xpl[lane] * ur[lane] + xpl[lane + 32] * ur[lane + 32];
        v1 = xmi[lane] * ur[lane] + xmi[lane + 32] * ur[lane + 32];
    } else {
        v0 = xmi[lane] * ur[lane] + xmi[lane + 32] * ur[lane + 32];
        v1 = xpl[lane] * ur[lane] + xpl[lane + 32] * ur[lane + 32];
    }
    #pragma unroll
    for (int o = 16; o > 0; o >>= 1) {
        v0 += __shfl_down_sync(FULLM, v0, o);
        v1 += __shfl_down_sync(FULLM, v1, o);
    }
    if (lane == 0) {
        float* dst = (row < NN) ? ret : reta;
        dst[(size_t)r * 2 + 0] = v0 + b[0];
        dst[(size_t)r * 2 + 1] = v1 + b[0];
    }
}

// ---------------- host ----------------
static void* sym(const void* s) {
    void* p = nullptr;
    cudaGetSymbolAddress(&p, s);
    return p;
}

extern "C" void kernel_launch(void* const* d_in, const int* in_sizes, int n_in,
                              void* d_out, int out_size) {
    const float* feat   = (const float*)d_in[0];
    const float* feat_a = (const float*)d_in[1];
    const float* adj    = (const float*)d_in[2];
    const float* gn     = (const float*)d_in[3];
    const float* w1     = (const float*)d_in[4];
    const float* w2     = (const float*)d_in[5];
    const float* attW   = (const float*)d_in[6];
    const float* a_src  = (const float*)d_in[7];
    const float* a_dst  = (const float*)d_in[8];
    const float* mW1 = (const float*)d_in[9];  const float* mb1 = (const float*)d_in[10];
    const float* mW2 = (const float*)d_in[11]; const float* mb2 = (const float*)d_in[12];
    const float* mW3 = (const float*)d_in[13]; const float* mb3 = (const float*)d_in[14];
    const float* dW1 = (const float*)d_in[15]; const float* db1 = (const float*)d_in[16];
    const float* dW2 = (const float*)d_in[17]; const float* db2 = (const float*)d_in[18];
    const float* bilW = (const float*)d_in[19];
    const float* bilb = (const float*)d_in[20];

    float* out      = (float*)d_out;
    float* out_h    = out + (size_t)NN * FOUT;
    float* out_ret  = out_h + (size_t)NN * FIN;
    float* out_reta = out_ret + (size_t)NN * 2;

    float* w1p  = (float*)sym(g_w1p);
    float* Wh   = (float*)sym(g_Wh);
    float* sv   = (float*)sym(g_s);
    float* dv   = (float*)sym(g_d);
    float* att  = (float*)sym(g_att);
    float* t1   = (float*)sym(g_t1);
    float* t2   = (float*)sym(g_t2);
    float* adjz = (float*)sym(g_adjz);
    float* dcat = (float*)sym(g_dcat);
    float* dh   = (float*)sym(g_dh);
    float* qcat = (float*)sym(g_qcat);
    float* u    = (float*)sym(g_u);
    float* part = (float*)sym(g_part);
    float* Bhi  = (float*)sym(g_Bhi);
    float* Blo  = (float*)sym(g_Blo);
    int* aidx = (int*)sym(g_adj_idx); int* acnt = (int*)sym(g_adj_cnt);
    int* gidx = (int*)sym(g_gn_idx);  int* gcnt = (int*)sym(g_gn_cnt);

    const int M2 = 2 * NN;   // 8192
    const int M4 = 4 * NN;   // 16384
    const long long PS = (long long)NN * FOUT;

    // 1. sparse lists + w1p = w1 @ attW + weight split (bilW transposed in split)
    build_list_kernel<<<dim3(NN, 2), 256>>>(adj, aidx, acnt, gn, gidx, gcnt);
    fold_w1_kernel<<<(FIN + 3) / 4, 256>>>(w1, attW, w1p);
    {
        SplitArgs sa;
        sa.src[0] = w1p;  sa.n[0] = FIN * FOUT;  sa.off[0] = OFF_W1;  sa.tr[0] = 0;
        sa.src[1] = w2;   sa.n[1] = FOUT * FIN;  sa.off[1] = OFF_W2;  sa.tr[1] = 0;
        sa.src[2] = mW1;  sa.n[2] = 64 * 256;    sa.off[2] = OFF_MW1; sa.tr[2] = 0;
        sa.src[3] = mW2;  sa.n[3] = 256 * 128;   sa.off[3] = OFF_MW2; sa.tr[3] = 0;
        sa.src[4] = mW3;  sa.n[4] = 128 * 64;    sa.off[4] = OFF_MW3; sa.tr[4] = 0;
        sa.src[5] = dW1;  sa.n[5] = 64 * 128;    sa.off[5] = OFF_DW1; sa.tr[5] = 0;
        sa.src[6] = dW2;  sa.n[6] = 128 * 64;    sa.off[6] = OFF_DW2; sa.tr[6] = 0;
        sa.src[7] = bilW; sa.n[7] = 64 * 64;     sa.off[7] = OFF_WT;  sa.tr[7] = 1;
        split_kernel<<<dim3((FIN * FOUT + 255) / 256, 8), 256>>>(sa, Bhi, Blo);
    }

    // 2. part = [feat; feat_a] @ w1p  (cp.async tf32, split-K=6 -> 384 CTAs)
    gemm_cp<<<dim3(1, NN / 128, 2 * KSPL), 256>>>(
        feat, feat_a, Bhi + OFF_W1, part, NN, FOUT, FIN, 512, KSPL, PS);
    // fused reduce -> Wh (2NN x 64) + s/d row dots
    reduce_sd_kernel<<<(M2 * FOUT) / 256, 256>>>(part, a_src, a_dst, Wh, sv, dv);

    // 3. attention + MLP over 8192 rows (3xtf32)
    att_warp_kernel<<<M2 / 8, 256>>>(aidx, acnt, sv, dv, Wh, att);
    gemm_tc3<4, 16><<<dim3(4, M2 / 64, 1), 128>>>(att, Bhi + OFF_MW1, Blo + OFF_MW1,
                                                  mb1, t1, nullptr, M2, 256, 64, 1);
    gemm_tc3<4, 16><<<dim3(2, M2 / 64, 1), 128>>>(t1, Bhi + OFF_MW2, Blo + OFF_MW2,
                                                  mb2, t2, nullptr, M2, 128, 256, 1);
    // MLP3: raw -> out (rows < NN = hiden_emb/z), relu -> dcat[8192..16383]
    gemm_tc3<4, 16><<<dim3(1, M2 / 64, 1), 128>>>(t2, Bhi + OFF_MW3, Blo + OFF_MW3,
                                                  mb3, out, dcat + (size_t)M2 * FOUT,
                                                  M2, 64, 128, 3);

    // 4. h = (adj @ z) @ w2  (z read from d_out; cp.async tf32)
    agg_warp_kernel<<<NN / 8, 256>>>(aidx, acnt, out, adjz);
    gemm_cp<<<dim3((FIN + 63) / 64, NN / 128, 1), 256>>>(
        adjz, nullptr, Bhi + OFF_W2, out_h, NN, FIN, FOUT, FOUT, 1, 0);

    // 5. readouts -> dcat[0..8191] = [gv; gva]
    readout_warp_kernel<<<M2 / 8, 256>>>(gidx, gcnt, dcat);

    // 6. discriminator MLP over all 16384 rows -> qcat = [dc; dca; dpl; dmi]
    gemm_tc3<4, 16><<<dim3(2, M4 / 64, 1), 128>>>(dcat, Bhi + OFF_DW1, Blo + OFF_DW1,
                                                  db1, dh, nullptr, M4, 128, 64, 1);
    gemm_tc3<4, 16><<<dim3(1, M4 / 64, 1), 128>>>(dh, Bhi + OFF_DW2, Blo + OFF_DW2,
                                                  db2, qcat, nullptr, M4, 64, 128, 0);

    // 7. bilinear
    gemm_tc3<4, 16><<<dim3(1, M2 / 64, 1), 128>>>(qcat, Bhi + OFF_WT, Blo + OFF_WT,
                                                  nullptr, u, nullptr, M2, 64, 64, 0);
    bilin_warp_kernel<<<M2 / 8, 256>>>(qcat, u, bilb, out_ret, out_reta);
}

// round 14
// speedup vs baseline: 1.2711x; 1.0048x over previous
#include <cuda_runtime.h>
#include <stdint.h>
#include <math.h>
#include <mma.h>

using namespace nvcuda;

#define NN 4096
#define FIN 3000
#define FOUT 64
#define MAXNNZ 512
#define KSPL 6
#define FULLM 0xffffffffu

// ---------------- scratch (static device memory; no allocation) ----------------
__device__ float g_Wh  [2*NN*FOUT];
__device__ float g_s   [2*NN];
__device__ float g_d   [2*NN];
__device__ float g_att [2*NN*FOUT];
__device__ float g_t1  [2*NN*256];
__device__ float g_t2  [2*NN*128];
__device__ float g_adjz[NN*FOUT];
__device__ float g_dcat[4*NN*FOUT];      // [gv; gva; emb; emba]
__device__ float g_dh  [4*NN*128];
__device__ float g_qcat[4*NN*FOUT];      // [dc; dca; dpl; dmi]
__device__ float g_u   [2*NN*FOUT];      // [u; ua]
__device__ float g_part[2*KSPL*NN*FOUT];
__device__ int   g_adj_idx[NN*MAXNNZ];
__device__ int   g_adj_cnt[NN];
__device__ int   g_gn_idx [NN*MAXNNZ];
__device__ int   g_gn_cnt [NN];

// precomputed tf32 hi/lo weight buffers (concatenated)
#define OFF_W1   0
#define OFF_W2   192000
#define OFF_MW1  384000
#define OFF_MW2  400384
#define OFF_MW3  433152
#define OFF_DW1  441344
#define OFF_DW2  449536
#define OFF_WT   457728
#define SPLIT_TOTAL 461824
__device__ float g_Bhi[SPLIT_TOTAL];
__device__ float g_Blo[SPLIT_TOTAL];

__device__ __forceinline__ float t32(float x) { return wmma::__float_to_tf32(x); }

__device__ __forceinline__ uint32_t s2u(const void* p) {
    return (uint32_t)__cvta_generic_to_shared(p);
}
__device__ __forceinline__ void cpa16(uint32_t dst, const void* src, int bytes) {
    asm volatile("cp.async.cg.shared.global [%0], [%1], 16, %2;"
                 :: "r"(dst), "l"(src), "r"(bytes));
}

// ---------------- fold w1@attW directly into hi/lo split ----------------------
__global__ void fold_w1_kernel(const float* __restrict__ w1, const float* __restrict__ attW,
                               float* __restrict__ hi, float* __restrict__ lo) {
    __shared__ float aw[64][65];
    __shared__ float wr[4][64];
    int tid = threadIdx.x;
    int row0 = blockIdx.x * 4;
    for (int t = tid; t < 4096; t += 256) aw[t >> 6][t & 63] = attW[t];
    {
        int r = tid >> 6, c = tid & 63;
        int gr = row0 + r;
        wr[r][c] = (gr < FIN) ? w1[(size_t)gr * 64 + c] : 0.0f;
    }
    __syncthreads();
    int r = tid >> 6, c = tid & 63;
    float acc = 0.0f;
    #pragma unroll
    for (int k = 0; k < 64; k++) acc += wr[r][k] * aw[k][c];
    int gr = row0 + r;
    if (gr < FIN) {
        float h = t32(acc);
        hi[OFF_W1 + (size_t)gr * 64 + c] = h;
        lo[OFF_W1 + (size_t)gr * 64 + c] = t32(acc - h);
    }
}

// ---------------- weight hi/lo split (7 segments, opt transpose) --------------
struct SplitArgs {
    const float* src[7];
    int n[7];
    int off[7];
    int tr[7];   // transpose 64x64
};
__global__ void split_kernel(SplitArgs a, float* __restrict__ hi, float* __restrict__ lo) {
    int seg = blockIdx.y;
    int i = blockIdx.x * 256 + threadIdx.x;
    if (i < a.n[seg]) {
        float x = a.tr[seg] ? a.src[seg][(i & 63) * 64 + (i >> 6)] : a.src[seg][i];
        float h = t32(x);
        hi[a.off[seg] + i] = h;
        lo[a.off[seg] + i] = t32(x - h);
    }
}

// ---------------- build sparse row lists (both matrices, one launch) ----------
__global__ void build_list_kernel(const float* __restrict__ matA, int* __restrict__ idxA,
                                  int* __restrict__ cntA,
                                  const float* __restrict__ matB, int* __restrict__ idxB,
                                  int* __restrict__ cntB) {
    int row = blockIdx.x;
    const float* mat = blockIdx.y ? matB : matA;
    int* idx = blockIdx.y ? idxB : idxA;
    int* cnt = blockIdx.y ? cntB : cntA;
    int tid = threadIdx.x;
    int wid = tid >> 5, lane = tid & 31;
    const float4* r4 = (const float4*)(mat + (size_t)row * NN);
    __shared__ int wsum[8];
    __shared__ int woff[8];
    float v[16];
    #pragma unroll
    for (int q = 0; q < 4; q++) {
        float4 x = r4[tid * 4 + q];
        v[q * 4 + 0] = x.x; v[q * 4 + 1] = x.y; v[q * 4 + 2] = x.z; v[q * 4 + 3] = x.w;
    }
    int base = tid * 16;
    int c = 0;
    #pragma unroll
    for (int j = 0; j < 16; j++) c += (v[j] != 0.0f);
    int inc = c;
    #pragma unroll
    for (int o = 1; o < 32; o <<= 1) {
        int t = __shfl_up_sync(FULLM, inc, o);
        if (lane >= o) inc += t;
    }
    if (lane == 31) wsum[wid] = inc;
    __syncthreads();
    if (tid < 8) {
        int t = wsum[tid];
        int iv = t;
        #pragma unroll
        for (int o = 1; o < 8; o <<= 1) {
            int u = __shfl_up_sync(0xffu, iv, o);
            if (tid >= o) iv += u;
        }
        woff[tid] = iv - t;
        if (tid == 7) cnt[row] = iv;
    }
    __syncthreads();
    int o = woff[wid] + inc - c;
    int* dst = idx + (size_t)row * MAXNNZ;
    #pragma unroll
    for (int j = 0; j < 16; j++) {
        if (v[j] != 0.0f) dst[o++] = base + j;
    }
}

// ---------------- plain-tf32 GEMM, 3-stage cp.async pipeline ------------------
// C = A[M,K] @ B[K,N]. BM=128, BN=64, BK=16, 256 threads.
// A raw fp32 via cp.async; tf32 RN conversion on fragment registers.
// B = precomputed tf32 hi. split-K via blockIdx.z; bz >= kspl uses A2.
// Shared arena: 3 stages of (A-tile 10240B + B-tile 4608B); the C-writeback
// buffer aliases stage 0 after the mainloop (guarded by __syncthreads).
#define STG_A 10240
#define STG_B 4608
#define STG   (STG_A + STG_B)
__global__ __launch_bounds__(256, 3)
void gemm_cp(const float* __restrict__ A, const float* __restrict__ A2,
             const float* __restrict__ Bhi, float* __restrict__ C,
             int M, int N, int K, int kChunk, int kspl, long long partStride) {
    constexpr int BK = 16;
    constexpr int LDA = 20;
    __shared__ char arena[3 * STG];
    auto AhS = [&](int s) { return (float(*)[LDA])(arena + s * STG); };
    auto BhS = [&](int s) { return (float(*)[72])(arena + s * STG + STG_A); };

    int bz = blockIdx.z;
    int kz = bz % kspl;
    const float* Asrc = (bz < kspl) ? A : A2;
    int k0 = kz * kChunk;
    int k1 = min(K, k0 + kChunk);
    float* Cp = C + (long long)bz * partStride;
    int row0 = blockIdx.y * 128;
    int col0 = blockIdx.x * 64;
    int tid = threadIdx.x;
    int wid = tid >> 5;
    int lane = tid & 31;

    wmma::fragment<wmma::accumulator, 16, 16, 8, float> acc[4];
    #pragma unroll
    for (int f = 0; f < 4; f++) wmma::fill_fragment(acc[f], 0.0f);

    auto loadTiles = [&](int s, int kk) {
        float (*Ah)[LDA] = AhS(s);
        float (*Bh)[72] = BhS(s);
        #pragma unroll
        for (int v = 0; v < 2; v++) {
            int id = tid + v * 256;
            int row = id >> 2, c4 = id & 3;
            int gk = kk + c4 * 4;
            int bytes = (k1 - gk) * 4;
            bytes = bytes < 0 ? 0 : (bytes > 16 ? 16 : bytes);
            const float* src = Asrc + (size_t)(row0 + row) * K + (bytes > 0 ? gk : k0);
            cpa16(s2u(&Ah[row][c4 * 4]), src, bytes);
        }
        {
            int row = tid >> 4, c4 = tid & 15;
            int gk = kk + row;
            int gn = col0 + c4 * 4;
            int bytes = 0;
            if (gk < k1) {
                bytes = (N - gn) * 4;
                bytes = bytes < 0 ? 0 : (bytes > 16 ? 16 : bytes);
            }
            const float* src = Bhi + (size_t)(bytes > 0 ? gk : k0) * N
                                   + (bytes > 0 ? gn : col0);
            cpa16(s2u(&Bh[row][c4 * 4]), src, bytes);
        }
        asm volatile("cp.async.commit_group;");
    };

    int nIter = (k1 - k0 + BK - 1) / BK;
    loadTiles(0, k0);
    if (nIter > 1) loadTiles(1, k0 + BK);
    for (int it = 0; it < nIter; it++) {
        if (it + 2 < nIter) {
            loadTiles((it + 2) % 3, k0 + (it + 2) * BK);
            asm volatile("cp.async.wait_group 2;");
        } else if (it + 1 < nIter) {
            asm volatile("cp.async.wait_group 1;");
        } else {
            asm volatile("cp.async.wait_group 0;");
        }
        __syncthreads();
        int s = it % 3;
        float (*Ah)[LDA] = AhS(s);
        float (*Bh)[72] = BhS(s);
        #pragma unroll
        for (int ks = 0; ks < BK; ks += 8) {
            wmma::fragment<wmma::matrix_a, 16, 16, 8, wmma::precision::tf32, wmma::row_major> ah;
            wmma::load_matrix_sync(ah, &Ah[wid * 16][ks], LDA);
            #pragma unroll
            for (int i = 0; i < ah.num_elements; i++) ah.x[i] = t32(ah.x[i]);
            #pragma unroll
            for (int f = 0; f < 4; f++) {
                wmma::fragment<wmma::matrix_b, 16, 16, 8, wmma::precision::tf32, wmma::row_major> bh;
                wmma::load_matrix_sync(bh, &Bh[ks][f * 16], 72);
                wmma::mma_sync(acc[f], ah, bh, acc[f]);
            }
        }
        __syncthreads();
    }

    // epilogue: Cb aliases the arena (all loads/computes done, sync above)
    float (*Cb)[256] = (float(*)[256])arena;
    int r0 = row0 + wid * 16;
    #pragma unroll
    for (int f = 0; f < 4; f++) {
        int c0 = col0 + f * 16;
        __syncwarp();
        wmma::store_matrix_sync(&Cb[wid][0], acc[f], 16, wmma::mem_row_major);
        __syncwarp();
        for (int e = lane; e < 256; e += 32) {
            int rr = e >> 4, cc = e & 15;
            int c = c0 + cc;
            if (c < N) Cp[(size_t)(r0 + rr) * N + c] = Cb[wid][e];
        }
    }
}

// ---------------- 3xtf32 WMMA GEMM (proven small-GEMM config) -----------------
// C = act(A[M,K] @ B[K,N] + bias). BM=WARPS*16, BN=64, threads=WARPS*32.
// act: 0 none, 1 relu, 2 raw->C + relu->C2, 3 raw->C only rows<NN + relu->C2.
template<int WARPS, int BK>
__global__ __launch_bounds__(WARPS * 32, 4)
void gemm_tc3(const float* __restrict__ A,
              const float* __restrict__ Bhi, const float* __restrict__ Blo,
              const float* __restrict__ bias, float* __restrict__ C,
              float* __restrict__ C2, int M, int N, int K, int act) {
    constexpr int BM = WARPS * 16;
    constexpr int TPB = WARPS * 32;
    constexpr int CPT = BM * BK / TPB;
    constexpr int AFR = CPT / 4;
    constexpr int BROWS = TPB / 16;
    constexpr int BITER = BK / BROWS;
    constexpr int LDA = BK + 4;

    int row0 = blockIdx.y * BM;
    int col0 = blockIdx.x * 64;
    int tid = threadIdx.x;
    int wid = tid >> 5;
    int lane = tid & 31;

    __shared__ float Ah[BM][LDA];
    __shared__ float Al[BM][LDA];
    __shared__ float Bh[BK][72];
    __shared__ float Bl[BK][72];
    __shared__ float Cb[WARPS][256];

    wmma::fragment<wmma::accumulator, 16, 16, 8, float> acc[4];
    #pragma unroll
    for (int f = 0; f < 4; f++) wmma::fill_fragment(acc[f], 0.0f);

    int ar = tid >> 1;
    int acb = (tid & 1) * CPT;
    const float* Arow = A + (size_t)(row0 + ar) * K;
    int bn = (tid & 15) * 4;
    int bkb = tid >> 4;
    int gnB = col0 + bn;

    float4 aR[AFR], bhR[BITER], blR[BITER];
    const float4 f4z = make_float4(0.f, 0.f, 0.f, 0.f);

    auto loadTiles = [&](int kk) {
        #pragma unroll
        for (int v = 0; v < AFR; v++) {
            int gk = kk + acb + v * 4;
            aR[v] = (gk < K) ? *(const float4*)(Arow + gk) : f4z;
        }
        #pragma unroll
        for (int i = 0; i < BITER; i++) {
            int gkb = kk + bkb + i * BROWS;
            bhR[i] = f4z;
            blR[i] = f4z;
            if (gkb < K && gnB < N) {
                bhR[i] = *(const float4*)(Bhi + (size_t)gkb * N + gnB);
                blR[i] = *(const float4*)(Blo + (size_t)gkb * N + gnB);
            }
        }
    };
    auto storeTiles = [&]() {
        #pragma unroll
        for (int v = 0; v < AFR; v++) {
            int c = acb + v * 4;
            float* dh = &Ah[ar][c];
            float* dl = &Al[ar][c];
            float h;
            h = t32(aR[v].x); dh[0] = h; dl[0] = t32(aR[v].x - h);
            h = t32(aR[v].y); dh[1] = h; dl[1] = t32(aR[v].y - h);
            h = t32(aR[v].z); dh[2] = h; dl[2] = t32(aR[v].z - h);
            h = t32(aR[v].w); dh[3] = h; dl[3] = t32(aR[v].w - h);
        }
        #pragma unroll
        for (int i = 0; i < BITER; i++) {
            *(float4*)&Bh[bkb + i * BROWS][bn] = bhR[i];
            *(float4*)&Bl[bkb + i * BROWS][bn] = blR[i];
        }
    };

    loadTiles(0);
    for (int kk = 0; kk < K; kk += BK) {
        storeTiles();
        __syncthreads();
        int nk = kk + BK;
        if (nk < K) loadTiles(nk);
        #pragma unroll
        for (int ks = 0; ks < BK; ks += 8) {
            wmma::fragment<wmma::matrix_a, 16, 16, 8, wmma::precision::tf32, wmma::row_major> ah, al;
            wmma::load_matrix_sync(ah, &Ah[wid * 16][ks], LDA);
            wmma::load_matrix_sync(al, &Al[wid * 16][ks], LDA);
            #pragma unroll
            for (int f = 0; f < 4; f++) {
                wmma::fragment<wmma::matrix_b, 16, 16, 8, wmma::precision::tf32, wmma::row_major> bh, bl;
                wmma::load_matrix_sync(bh, &Bh[ks][f * 16], 72);
                wmma::load_matrix_sync(bl, &Bl[ks][f * 16], 72);
                wmma::mma_sync(acc[f], ah, bl, acc[f]);
                wmma::mma_sync(acc[f], al, bh, acc[f]);
                wmma::mma_sync(acc[f], ah, bh, acc[f]);
            }
        }
        __syncthreads();
    }

    int r0 = row0 + wid * 16;
    #pragma unroll
    for (int f = 0; f < 4; f++) {
        int c0 = col0 + f * 16;
        __syncwarp();
        wmma::store_matrix_sync(&Cb[wid][0], acc[f], 16, wmma::mem_row_major);
        __syncwarp();
        for (int e = lane; e < 256; e += 32) {
            int rr = e >> 4, cc = e & 15;
            int c = c0 + cc;
            if (c < N) {
                float v = Cb[wid][e];
                if (bias) v += bias[c];
                int gr = r0 + rr;
                size_t oi = (size_t)gr * N + c;
                if (act == 0) {
                    C[oi] = v;
                } else if (act == 1) {
                    C[oi] = fmaxf(v, 0.0f);
                } else if (act == 2) {
                    C[oi] = v;
                    C2[oi] = fmaxf(v, 0.0f);
                } else {  // act == 3
                    if (gr < NN) C[oi] = v;
                    C2[oi] = fmaxf(v, 0.0f);
                }
            }
        }
    }
}

// ---------------- fused split-K reduce -> Wh, plus s/d row dots ---------------
__global__ void reduce_sd_kernel(const float* __restrict__ part,
                                 const float* __restrict__ a_src,
                                 const float* __restrict__ a_dst,
                                 float* __restrict__ Wh, float* __restrict__ s,
                                 float* __restrict__ d) {
    const int HALF = NN * FOUT;
    int i = blockIdx.x * 256 + threadIdx.x;
    int h = i >= HALF;
    int j = i - h * HALF;
    const float* base = part + (size_t)h * KSPL * HALF;
    float v = 0.0f;
    #pragma unroll
    for (int z = 0; z < KSPL; z++) v += base[(size_t)z * HALF + j];
    Wh[i] = v;
    int col = i & 63;
    float vs = v * a_src[col];
    float vd = v * a_dst[col];
    #pragma unroll
    for (int o = 16; o > 0; o >>= 1) {
        vs += __shfl_down_sync(FULLM, vs, o);
        vd += __shfl_down_sync(FULLM, vd, o);
    }
    __shared__ float sh[2][8];
    int wid = threadIdx.x >> 5;
    if ((threadIdx.x & 31) == 0) { sh[0][wid] = vs; sh[1][wid] = vd; }
    __syncthreads();
    if ((threadIdx.x & 63) == 0) {
        int row = i >> 6;
        s[row] = sh[0][wid] + sh[0][wid + 1];
        d[row] = sh[1][wid] + sh[1][wid + 1];
    }
}

// ---------------- warp-per-row attention (online softmax), 8192 rows ----------
__global__ void att_warp_kernel(const int* __restrict__ idx, const int* __restrict__ cnt,
                                const float* __restrict__ s, const float* __restrict__ d,
                                const float* __restrict__ Wh, float* __restrict__ out) {
    int row = blockIdx.x * 8 + (threadIdx.x >> 5);
    int lane = threadIdx.x & 31;
    if (row >= 2 * NN) return;
    int grow = row & (NN - 1);
    int off = row & NN;
    int n = cnt[grow];
    const int* lst = idx + (size_t)grow * MAXNNZ;
    float si = s[row];
    float m = -3.4e38f, ssum = 0.0f, a0 = 0.0f, a1 = 0.0f;
    for (int base = 0; base < n; base += 32) {
        int t = base + lane;
        int j = 0;
        float e = -3.4e38f;
        if (t < n) {
            j = lst[t];
            float v = si + d[j + off];
            e = v > 0.0f ? v : 0.2f * v;
        }
        float cm = e;
        #pragma unroll
        for (int o = 16; o > 0; o >>= 1) cm = fmaxf(cm, __shfl_xor_sync(FULLM, cm, o));
        float nm = fmaxf(m, cm);
        float scale = expf(m - nm);
        a0 *= scale; a1 *= scale; ssum *= scale;
        float w = (t < n) ? expf(e - nm) : 0.0f;
        float cs = w;
        #pragma unroll
        for (int o = 16; o > 0; o >>= 1) cs += __shfl_xor_sync(FULLM, cs, o);
        ssum += cs;
        int lim = min(32, n - base);
        for (int q = 0; q < lim; q++) {
            float wq = __shfl_sync(FULLM, w, q);
            int jq = __shfl_sync(FULLM, j, q);
            const float* r = Wh + (size_t)(jq + off) * 64;
            a0 += wq * r[lane];
            a1 += wq * r[lane + 32];
        }
        m = nm;
    }
    float inv = 1.0f / ssum;
    out[(size_t)row * 64 + lane] = a0 * inv;
    out[(size_t)row * 64 + lane + 32] = a1 * inv;
}

// ---------------- adjz = adj @ z (warp per row; z lives in d_out) -------------
__global__ void agg_warp_kernel(const int* __restrict__ idx, const int* __restrict__ cnt,
                                const float* __restrict__ z, float* __restrict__ out) {
    int row = blockIdx.x * 8 + (threadIdx.x >> 5);
    int lane = threadIdx.x & 31;
    if (row >= NN) return;
    int n = cnt[row];
    const int* lst = idx + (size_t)row * MAXNNZ;
    float a0 = 0.0f, a1 = 0.0f;
    for (int base = 0; base < n; base += 32) {
        int t = base + lane;
        int j = (t < n) ? lst[t] : 0;
        int lim = min(32, n - base);
        for (int q = 0; q < lim; q++) {
            int jq = __shfl_sync(FULLM, j, q);
            const float* r = z + (size_t)jq * 64;
            a0 += r[lane];
            a1 += r[lane + 32];
        }
    }
    out[(size_t)row * 64 + lane] = a0;
    out[(size_t)row * 64 + lane + 32] = a1;
}

// ---------------- warp-per-row readout: mean, L2-norm, sigmoid (8192 rows) ----
__global__ void readout_warp_kernel(const int* __restrict__ idx, const int* __restrict__ cnt,
                                    float* __restrict__ dcat) {
    int row = blockIdx.x * 8 + (threadIdx.x >> 5);
    int lane = threadIdx.x & 31;
    if (row >= 2 * NN) return;
    int grow = row & (NN - 1);
    int n = cnt[grow];
    const int* lst = idx + (size_t)grow * MAXNNZ;
    int off = (row < NN) ? 2 * NN : 3 * NN;
    float a0 = 0.0f, a1 = 0.0f;
    for (int base = 0; base < n; base += 32) {
        int t = base + lane;
        int j = (t < n) ? lst[t] : 0;
        int lim = min(32, n - base);
        for (int q = 0; q < lim; q++) {
            int jq = __shfl_sync(FULLM, j, q);
            const float* r = dcat + (size_t)(off + jq) * 64;
            a0 += r[lane];
            a1 += r[lane + 32];
        }
    }
    float invn = 1.0f / (float)n;
    float v0 = a0 * invn, v1 = a1 * invn;
    float ss = v0 * v0 + v1 * v1;
    #pragma unroll
    for (int o = 16; o > 0; o >>= 1) ss += __shfl_xor_sync(FULLM, ss, o);
    float den = fmaxf(sqrtf(ss), 1e-12f);
    float x0 = v0 / den, x1 = v1 / den;
    dcat[(size_t)row * 64 + lane] = 1.0f / (1.0f + expf(-x0));
    dcat[(size_t)row * 64 + lane + 32] = 1.0f / (1.0f + expf(-x1));
}

// ---------------- bilinear outputs (warp per logical row, 8192 rows) ----------
__global__ void bilin_warp_kernel(const float* __restrict__ qcat, const float* __restrict__ u,
                                  const float* __restrict__ b, float* __restrict__ ret,
                                  float* __restrict__ reta) {
    int row = blockIdx.x * 8 + (threadIdx.x >> 5);
    int lane = threadIdx.x & 31;
    if (row >= 2 * NN) return;
    int r = row & (NN - 1);
    const float* ur = u + (size_t)row * 64;
    const float* xpl = qcat + (size_t)(2 * NN + r) * 64;
    const float* xmi = qcat + (size_t)(3 * NN + r) * 64;
    float v0, v1;
    if (row < NN) {
        v0 = xpl[lane] * ur[lane] + xpl[lane + 32] * ur[lane + 32];
        v1 = xmi[lane] * ur[lane] + xmi[lane + 32] * ur[lane + 32];
    } else {
        v0 = xmi[lane] * ur[lane] + xmi[lane + 32] * ur[lane + 32];
        v1 = xpl[lane] * ur[lane] + xpl[lane + 32] * ur[lane + 32];
    }
    #pragma unroll
    for (int o = 16; o > 0; o >>= 1) {
        v0 += __shfl_down_sync(FULLM, v0, o);
        v1 += __shfl_down_sync(FULLM, v1, o);
    }
    if (lane == 0) {
        float* dst = (row < NN) ? ret : reta;
        dst[(size_t)r * 2 + 0] = v0 + b[0];
        dst[(size_t)r * 2 + 1] = v1 + b[0];
    }
}

// ---------------- host ----------------
static void* sym(const void* s) {
    void* p = nullptr;
    cudaGetSymbolAddress(&p, s);
    return p;
}

extern "C" void kernel_launch(void* const* d_in, const int* in_sizes, int n_in,
                              void* d_out, int out_size) {
    const float* feat   = (const float*)d_in[0];
    const float* feat_a = (const float*)d_in[1];
    const float* adj    = (const float*)d_in[2];
    const float* gn     = (const float*)d_in[3];
    const float* w1     = (const float*)d_in[4];
    const float* w2     = (const float*)d_in[5];
    const float* attW   = (const float*)d_in[6];
    const float* a_src  = (const float*)d_in[7];
    const float* a_dst  = (const float*)d_in[8];
    const float* mW1 = (const float*)d_in[9];  const float* mb1 = (const float*)d_in[10];
    const float* mW2 = (const float*)d_in[11]; const float* mb2 = (const float*)d_in[12];
    const float* mW3 = (const float*)d_in[13]; const float* mb3 = (const float*)d_in[14];
    const float* dW1 = (const float*)d_in[15]; const float* db1 = (const float*)d_in[16];
    const float* dW2 = (const float*)d_in[17]; const float* db2 = (const float*)d_in[18];
    const float* bilW = (const float*)d_in[19];
    const float* bilb = (const float*)d_in[20];

    float* out      = (float*)d_out;
    float* out_h    = out + (size_t)NN * FOUT;
    float* out_ret  = out_h + (size_t)NN * FIN;
    float* out_reta = out_ret + (size_t)NN * 2;

    float* Wh   = (float*)sym(g_Wh);
    float* sv   = (float*)sym(g_s);
    float* dv   = (float*)sym(g_d);
    float* att  = (float*)sym(g_att);
    float* t1   = (float*)sym(g_t1);
    float* t2   = (float*)sym(g_t2);
    float* adjz = (float*)sym(g_adjz);
    float* dcat = (float*)sym(g_dcat);
    float* dh   = (float*)sym(g_dh);
    float* qcat = (float*)sym(g_qcat);
    float* u    = (float*)sym(g_u);
    float* part = (float*)sym(g_part);
    float* Bhi  = (float*)sym(g_Bhi);
    float* Blo  = (float*)sym(g_Blo);
    int* aidx = (int*)sym(g_adj_idx); int* acnt = (int*)sym(g_adj_cnt);
    int* gidx = (int*)sym(g_gn_idx);  int* gcnt = (int*)sym(g_gn_cnt);

    const int M2 = 2 * NN;   // 8192
    const int M4 = 4 * NN;   // 16384
    const long long PS = (long long)NN * FOUT;

    // 1. sparse lists + fused fold(w1@attW)->hi/lo + weight split (7 segments)
    build_list_kernel<<<dim3(NN, 2), 256>>>(adj, aidx, acnt, gn, gidx, gcnt);
    fold_w1_kernel<<<(FIN + 3) / 4, 256>>>(w1, attW, Bhi, Blo);
    {
        SplitArgs sa;
        sa.src[0] = w2;   sa.n[0] = FOUT * FIN;  sa.off[0] = OFF_W2;  sa.tr[0] = 0;
        sa.src[1] = mW1;  sa.n[1] = 64 * 256;    sa.off[1] = OFF_MW1; sa.tr[1] = 0;
        sa.src[2] = mW2;  sa.n[2] = 256 * 128;   sa.off[2] = OFF_MW2; sa.tr[2] = 0;
        sa.src[3] = mW3;  sa.n[3] = 128 * 64;    sa.off[3] = OFF_MW3; sa.tr[3] = 0;
        sa.src[4] = dW1;  sa.n[4] = 64 * 128;    sa.off[4] = OFF_DW1; sa.tr[4] = 0;
        sa.src[5] = dW2;  sa.n[5] = 128 * 64;    sa.off[5] = OFF_DW2; sa.tr[5] = 0;
        sa.src[6] = bilW; sa.n[6] = 64 * 64;     sa.off[6] = OFF_WT;  sa.tr[6] = 1;
        split_kernel<<<dim3((FOUT * FIN + 255) / 256, 7), 256>>>(sa, Bhi, Blo);
    }

    // 2. part = [feat; feat_a] @ w1p  (3-stage cp.async tf32, split-K=6)
    gemm_cp<<<dim3(1, NN / 128, 2 * KSPL), 256>>>(
        feat, feat_a, Bhi + OFF_W1, part, NN, FOUT, FIN, 512, KSPL, PS);
    // fused reduce -> Wh (2NN x 64) + s/d row dots
    reduce_sd_kernel<<<(M2 * FOUT) / 256, 256>>>(part, a_src, a_dst, Wh, sv, dv);

    // 3. attention + MLP over 8192 rows (3xtf32)
    att_warp_kernel<<<M2 / 8, 256>>>(aidx, acnt, sv, dv, Wh, att);
    gemm_tc3<4, 16><<<dim3(4, M2 / 64, 1), 128>>>(att, Bhi + OFF_MW1, Blo + OFF_MW1,
                                                  mb1, t1, nullptr, M2, 256, 64, 1);
    gemm_tc3<4, 16><<<dim3(2, M2 / 64, 1), 128>>>(t1, Bhi + OFF_MW2, Blo + OFF_MW2,
                                                  mb2, t2, nullptr, M2, 128, 256, 1);
    // MLP3: raw -> out (rows < NN = hiden_emb/z), relu -> dcat[8192..16383]
    gemm_tc3<4, 16><<<dim3(1, M2 / 64, 1), 128>>>(t2, Bhi + OFF_MW3, Blo + OFF_MW3,
                                                  mb3, out, dcat + (size_t)M2 * FOUT,
                                                  M2, 64, 128, 3);

    // 4. h = (adj @ z) @ w2  (z read from d_out; cp.async tf32)
    agg_warp_kernel<<<NN / 8, 256>>>(aidx, acnt, out, adjz);
    gemm_cp<<<dim3((FIN + 63) / 64, NN / 128, 1), 256>>>(
        adjz, nullptr, Bhi + OFF_W2, out_h, NN, FIN, FOUT, FOUT, 1, 0);

    // 5. readouts -> dcat[0..8191] = [gv; gva]
    readout_warp_kernel<<<M2 / 8, 256>>>(gidx, gcnt, dcat);

    // 6. discriminator MLP over all 16384 rows -> qcat = [dc; dca; dpl; dmi]
    gemm_tc3<4, 16><<<dim3(2, M4 / 64, 1), 128>>>(dcat, Bhi + OFF_DW1, Blo + OFF_DW1,
                                                  db1, dh, nullptr, M4, 128, 64, 1);
    gemm_tc3<4, 16><<<dim3(1, M4 / 64, 1), 128>>>(dh, Bhi + OFF_DW2, Blo + OFF_DW2,
                                                  db2, qcat, nullptr, M4, 64, 128, 0);

    // 7. bilinear
    gemm_tc3<4, 16><<<dim3(1, M2 / 64, 1), 128>>>(qcat, Bhi + OFF_WT, Blo + OFF_WT,
                                                  nullptr, u, nullptr, M2, 64, 64, 0);
    bilin_warp_kernel<<<M2 / 8, 256>>>(qcat, u, bilb, out_ret, out_reta);
}

// round 15
// speedup vs baseline: 1.5499x; 1.2194x over previous
#include <cuda_runtime.h>
#include <stdint.h>
#include <math.h>
#include <mma.h>

using namespace nvcuda;

#define NN 4096
#define FIN 3000
#define FOUT 64
#define MAXNNZ 512
#define KSPL 6
#define FULLM 0xffffffffu

// ---------------- scratch (static device memory; no allocation) ----------------
__device__ float g_Wh  [2*NN*FOUT];
__device__ float g_s   [2*NN];
__device__ float g_d   [2*NN];
__device__ float g_att [2*NN*FOUT];
__device__ float g_t1  [2*NN*256];
__device__ float g_t2  [2*NN*128];
__device__ float g_adjz[NN*FOUT];
__device__ float g_dcat[4*NN*FOUT];      // [gv; gva; emb; emba]
__device__ float g_dh  [4*NN*128];
__device__ float g_qcat[4*NN*FOUT];      // [dc; dca; dpl; dmi]
__device__ float g_u   [2*NN*FOUT];      // [u; ua]
__device__ float g_part[2*KSPL*NN*FOUT];
__device__ int   g_adj_idx[NN*MAXNNZ];
__device__ int   g_adj_cnt[NN];
__device__ int   g_gn_idx [NN*MAXNNZ];
__device__ int   g_gn_cnt [NN];

// precomputed tf32 hi/lo weight buffers (concatenated)
#define OFF_W1   0
#define OFF_W2   192000
#define OFF_MW1  384000
#define OFF_MW2  400384
#define OFF_MW3  433152
#define OFF_DW1  441344
#define OFF_DW2  449536
#define OFF_WT   457728
#define SPLIT_TOTAL 461824
__device__ float g_Bhi[SPLIT_TOTAL];
__device__ float g_Blo[SPLIT_TOTAL];

__device__ __forceinline__ float t32(float x) { return wmma::__float_to_tf32(x); }

__device__ __forceinline__ uint32_t s2u(const void* p) {
    return (uint32_t)__cvta_generic_to_shared(p);
}
__device__ __forceinline__ void cpa16(uint32_t dst, const void* src, int bytes) {
    asm volatile("cp.async.cg.shared.global [%0], [%1], 16, %2;"
                 :: "r"(dst), "l"(src), "r"(bytes));
}

// ---------------- fold w1@attW directly into hi/lo split ----------------------
__global__ void fold_w1_kernel(const float* __restrict__ w1, const float* __restrict__ attW,
                               float* __restrict__ hi, float* __restrict__ lo) {
    __shared__ float aw[64][65];
    __shared__ float wr[4][64];
    int tid = threadIdx.x;
    int row0 = blockIdx.x * 4;
    for (int t = tid; t < 4096; t += 256) aw[t >> 6][t & 63] = attW[t];
    {
        int r = tid >> 6, c = tid & 63;
        int gr = row0 + r;
        wr[r][c] = (gr < FIN) ? w1[(size_t)gr * 64 + c] : 0.0f;
    }
    __syncthreads();
    int r = tid >> 6, c = tid & 63;
    float acc = 0.0f;
    #pragma unroll
    for (int k = 0; k < 64; k++) acc += wr[r][k] * aw[k][c];
    int gr = row0 + r;
    if (gr < FIN) {
        float h = t32(acc);
        hi[OFF_W1 + (size_t)gr * 64 + c] = h;
        lo[OFF_W1 + (size_t)gr * 64 + c] = t32(acc - h);
    }
}

// ---------------- weight hi/lo split (7 segments, opt transpose) --------------
struct SplitArgs {
    const float* src[7];
    int n[7];
    int off[7];
    int tr[7];   // transpose 64x64
};
__global__ void split_kernel(SplitArgs a, float* __restrict__ hi, float* __restrict__ lo) {
    int seg = blockIdx.y;
    int i = blockIdx.x * 256 + threadIdx.x;
    if (i < a.n[seg]) {
        float x = a.tr[seg] ? a.src[seg][(i & 63) * 64 + (i >> 6)] : a.src[seg][i];
        float h = t32(x);
        hi[a.off[seg] + i] = h;
        lo[a.off[seg] + i] = t32(x - h);
    }
}

// ---------------- build sparse row lists (both matrices, one launch) ----------
__global__ void build_list_kernel(const float* __restrict__ matA, int* __restrict__ idxA,
                                  int* __restrict__ cntA,
                                  const float* __restrict__ matB, int* __restrict__ idxB,
                                  int* __restrict__ cntB) {
    int row = blockIdx.x;
    const float* mat = blockIdx.y ? matB : matA;
    int* idx = blockIdx.y ? idxB : idxA;
    int* cnt = blockIdx.y ? cntB : cntA;
    int tid = threadIdx.x;
    int wid = tid >> 5, lane = tid & 31;
    const float4* r4 = (const float4*)(mat + (size_t)row * NN);
    __shared__ int wsum[8];
    __shared__ int woff[8];
    float v[16];
    #pragma unroll
    for (int q = 0; q < 4; q++) {
        float4 x = r4[tid * 4 + q];
        v[q * 4 + 0] = x.x; v[q * 4 + 1] = x.y; v[q * 4 + 2] = x.z; v[q * 4 + 3] = x.w;
    }
    int base = tid * 16;
    int c = 0;
    #pragma unroll
    for (int j = 0; j < 16; j++) c += (v[j] != 0.0f);
    int inc = c;
    #pragma unroll
    for (int o = 1; o < 32; o <<= 1) {
        int t = __shfl_up_sync(FULLM, inc, o);
        if (lane >= o) inc += t;
    }
    if (lane == 31) wsum[wid] = inc;
    __syncthreads();
    if (tid < 8) {
        int t = wsum[tid];
        int iv = t;
        #pragma unroll
        for (int o = 1; o < 8; o <<= 1) {
            int u = __shfl_up_sync(0xffu, iv, o);
            if (tid >= o) iv += u;
        }
        woff[tid] = iv - t;
        if (tid == 7) cnt[row] = iv;
    }
    __syncthreads();
    int o = woff[wid] + inc - c;
    int* dst = idx + (size_t)row * MAXNNZ;
    #pragma unroll
    for (int j = 0; j < 16; j++) {
        if (v[j] != 0.0f) dst[o++] = base + j;
    }
}

// ---------------- plain-tf32 GEMM, 3-stage cp.async pipeline ------------------
// C = A[M,K] @ B[K,N]. BM=128, BN=64, BK=16, 256 threads.
#define STG_A 10240
#define STG_B 4608
#define STG   (STG_A + STG_B)
__global__ __launch_bounds__(256, 3)
void gemm_cp(const float* __restrict__ A, const float* __restrict__ A2,
             const float* __restrict__ Bhi, float* __restrict__ C,
             int M, int N, int K, int kChunk, int kspl, long long partStride) {
    constexpr int BK = 16;
    constexpr int LDA = 20;
    __shared__ char arena[3 * STG];
    auto AhS = [&](int s) { return (float(*)[LDA])(arena + s * STG); };
    auto BhS = [&](int s) { return (float(*)[72])(arena + s * STG + STG_A); };

    int bz = blockIdx.z;
    int kz = bz % kspl;
    const float* Asrc = (bz < kspl) ? A : A2;
    int k0 = kz * kChunk;
    int k1 = min(K, k0 + kChunk);
    float* Cp = C + (long long)bz * partStride;
    int row0 = blockIdx.y * 128;
    int col0 = blockIdx.x * 64;
    int tid = threadIdx.x;
    int wid = tid >> 5;
    int lane = tid & 31;

    wmma::fragment<wmma::accumulator, 16, 16, 8, float> acc[4];
    #pragma unroll
    for (int f = 0; f < 4; f++) wmma::fill_fragment(acc[f], 0.0f);

    auto loadTiles = [&](int s, int kk) {
        float (*Ah)[LDA] = AhS(s);
        float (*Bh)[72] = BhS(s);
        #pragma unroll
        for (int v = 0; v < 2; v++) {
            int id = tid + v * 256;
            int row = id >> 2, c4 = id & 3;
            int gk = kk + c4 * 4;
            int bytes = (k1 - gk) * 4;
            bytes = bytes < 0 ? 0 : (bytes > 16 ? 16 : bytes);
            const float* src = Asrc + (size_t)(row0 + row) * K + (bytes > 0 ? gk : k0);
            cpa16(s2u(&Ah[row][c4 * 4]), src, bytes);
        }
        {
            int row = tid >> 4, c4 = tid & 15;
            int gk = kk + row;
            int gn = col0 + c4 * 4;
            int bytes = 0;
            if (gk < k1) {
                bytes = (N - gn) * 4;
                bytes = bytes < 0 ? 0 : (bytes > 16 ? 16 : bytes);
            }
            const float* src = Bhi + (size_t)(bytes > 0 ? gk : k0) * N
                                   + (bytes > 0 ? gn : col0);
            cpa16(s2u(&Bh[row][c4 * 4]), src, bytes);
        }
        asm volatile("cp.async.commit_group;");
    };

    int nIter = (k1 - k0 + BK - 1) / BK;
    loadTiles(0, k0);
    if (nIter > 1) loadTiles(1, k0 + BK);
    for (int it = 0; it < nIter; it++) {
        if (it + 2 < nIter) {
            loadTiles((it + 2) % 3, k0 + (it + 2) * BK);
            asm volatile("cp.async.wait_group 2;");
        } else if (it + 1 < nIter) {
            asm volatile("cp.async.wait_group 1;");
        } else {
            asm volatile("cp.async.wait_group 0;");
        }
        __syncthreads();
        int s = it % 3;
        float (*Ah)[LDA] = AhS(s);
        float (*Bh)[72] = BhS(s);
        #pragma unroll
        for (int ks = 0; ks < BK; ks += 8) {
            wmma::fragment<wmma::matrix_a, 16, 16, 8, wmma::precision::tf32, wmma::row_major> ah;
            wmma::load_matrix_sync(ah, &Ah[wid * 16][ks], LDA);
            #pragma unroll
            for (int i = 0; i < ah.num_elements; i++) ah.x[i] = t32(ah.x[i]);
            #pragma unroll
            for (int f = 0; f < 4; f++) {
                wmma::fragment<wmma::matrix_b, 16, 16, 8, wmma::precision::tf32, wmma::row_major> bh;
                wmma::load_matrix_sync(bh, &Bh[ks][f * 16], 72);
                wmma::mma_sync(acc[f], ah, bh, acc[f]);
            }
        }
        __syncthreads();
    }

    float (*Cb)[256] = (float(*)[256])arena;
    int r0 = row0 + wid * 16;
    #pragma unroll
    for (int f = 0; f < 4; f++) {
        int c0 = col0 + f * 16;
        __syncwarp();
        wmma::store_matrix_sync(&Cb[wid][0], acc[f], 16, wmma::mem_row_major);
        __syncwarp();
        for (int e = lane; e < 256; e += 32) {
            int rr = e >> 4, cc = e & 15;
            int c = c0 + cc;
            if (c < N) Cp[(size_t)(r0 + rr) * N + c] = Cb[wid][e];
        }
    }
}

// ---------------- tf32 WMMA GEMM, PREC=1 or 3 (small GEMMs) -------------------
// C = act(A[M,K] @ B[K,N] + bias). BM=WARPS*16, BN=64, threads=WARPS*32.
// act: 0 none, 1 relu, 2 raw->C + relu->C2, 3 raw->C only rows<NN + relu->C2.
template<int PREC, int WARPS, int BK>
__global__ __launch_bounds__(WARPS * 32, 4)
void gemm_tc3(const float* __restrict__ A,
              const float* __restrict__ Bhi, const float* __restrict__ Blo,
              const float* __restrict__ bias, float* __restrict__ C,
              float* __restrict__ C2, int M, int N, int K, int act) {
    constexpr int BM = WARPS * 16;
    constexpr int TPB = WARPS * 32;
    constexpr int CPT = BM * BK / TPB;
    constexpr int AFR = CPT / 4;
    constexpr int BROWS = TPB / 16;
    constexpr int BITER = BK / BROWS;
    constexpr int LDA = BK + 4;

    int row0 = blockIdx.y * BM;
    int col0 = blockIdx.x * 64;
    int tid = threadIdx.x;
    int wid = tid >> 5;
    int lane = tid & 31;

    __shared__ float Ah[BM][LDA];
    __shared__ float Al[PREC == 3 ? BM : 1][LDA];
    __shared__ float Bh[BK][72];
    __shared__ float Bl[PREC == 3 ? BK : 1][72];
    __shared__ float Cb[WARPS][256];

    wmma::fragment<wmma::accumulator, 16, 16, 8, float> acc[4];
    #pragma unroll
    for (int f = 0; f < 4; f++) wmma::fill_fragment(acc[f], 0.0f);

    int ar = tid >> 1;
    int acb = (tid & 1) * CPT;
    const float* Arow = A + (size_t)(row0 + ar) * K;
    int bn = (tid & 15) * 4;
    int bkb = tid >> 4;
    int gnB = col0 + bn;

    float4 aR[AFR], bhR[BITER], blR[BITER];
    const float4 f4z = make_float4(0.f, 0.f, 0.f, 0.f);

    auto loadTiles = [&](int kk) {
        #pragma unroll
        for (int v = 0; v < AFR; v++) {
            int gk = kk + acb + v * 4;
            aR[v] = (gk < K) ? *(const float4*)(Arow + gk) : f4z;
        }
        #pragma unroll
        for (int i = 0; i < BITER; i++) {
            int gkb = kk + bkb + i * BROWS;
            bhR[i] = f4z;
            if (PREC == 3) blR[i] = f4z;
            if (gkb < K && gnB < N) {
                bhR[i] = *(const float4*)(Bhi + (size_t)gkb * N + gnB);
                if (PREC == 3) blR[i] = *(const float4*)(Blo + (size_t)gkb * N + gnB);
            }
        }
    };
    auto storeTiles = [&]() {
        #pragma unroll
        for (int v = 0; v < AFR; v++) {
            int c = acb + v * 4;
            float* dh = &Ah[ar][c];
            float* dl = &Al[PREC == 3 ? ar : 0][c];
            float h;
            h = t32(aR[v].x); dh[0] = h; if (PREC == 3) dl[0] = t32(aR[v].x - h);
            h = t32(aR[v].y); dh[1] = h; if (PREC == 3) dl[1] = t32(aR[v].y - h);
            h = t32(aR[v].z); dh[2] = h; if (PREC == 3) dl[2] = t32(aR[v].z - h);
            h = t32(aR[v].w); dh[3] = h; if (PREC == 3) dl[3] = t32(aR[v].w - h);
        }
        #pragma unroll
        for (int i = 0; i < BITER; i++) {
            *(float4*)&Bh[bkb + i * BROWS][bn] = bhR[i];
            if (PREC == 3) *(float4*)&Bl[bkb + i * BROWS][bn] = blR[i];
        }
    };

    loadTiles(0);
    for (int kk = 0; kk < K; kk += BK) {
        storeTiles();
        __syncthreads();
        int nk = kk + BK;
        if (nk < K) loadTiles(nk);
        #pragma unroll
        for (int ks = 0; ks < BK; ks += 8) {
            wmma::fragment<wmma::matrix_a, 16, 16, 8, wmma::precision::tf32, wmma::row_major> ah, al;
            wmma::load_matrix_sync(ah, &Ah[wid * 16][ks], LDA);
            if (PREC == 3) wmma::load_matrix_sync(al, &Al[wid * 16][ks], LDA);
            #pragma unroll
            for (int f = 0; f < 4; f++) {
                wmma::fragment<wmma::matrix_b, 16, 16, 8, wmma::precision::tf32, wmma::row_major> bh, bl;
                wmma::load_matrix_sync(bh, &Bh[ks][f * 16], 72);
                if (PREC == 3) {
                    wmma::load_matrix_sync(bl, &Bl[ks][f * 16], 72);
                    wmma::mma_sync(acc[f], ah, bl, acc[f]);
                    wmma::mma_sync(acc[f], al, bh, acc[f]);
                }
                wmma::mma_sync(acc[f], ah, bh, acc[f]);
            }
        }
        __syncthreads();
    }

    int r0 = row0 + wid * 16;
    #pragma unroll
    for (int f = 0; f < 4; f++) {
        int c0 = col0 + f * 16;
        __syncwarp();
        wmma::store_matrix_sync(&Cb[wid][0], acc[f], 16, wmma::mem_row_major);
        __syncwarp();
        for (int e = lane; e < 256; e += 32) {
            int rr = e >> 4, cc = e & 15;
            int c = c0 + cc;
            if (c < N) {
                float v = Cb[wid][e];
                if (bias) v += bias[c];
                int gr = r0 + rr;
                size_t oi = (size_t)gr * N + c;
                if (act == 0) {
                    C[oi] = v;
                } else if (act == 1) {
                    C[oi] = fmaxf(v, 0.0f);
                } else if (act == 2) {
                    C[oi] = v;
                    C2[oi] = fmaxf(v, 0.0f);
                } else {  // act == 3
                    if (gr < NN) C[oi] = v;
                    C2[oi] = fmaxf(v, 0.0f);
                }
            }
        }
    }
}

// ---------------- fused split-K reduce -> Wh, plus s/d row dots ---------------
__global__ void reduce_sd_kernel(const float* __restrict__ part,
                                 const float* __restrict__ a_src,
                                 const float* __restrict__ a_dst,
                                 float* __restrict__ Wh, float* __restrict__ s,
                                 float* __restrict__ d) {
    const int HALF = NN * FOUT;
    int i = blockIdx.x * 256 + threadIdx.x;
    int h = i >= HALF;
    int j = i - h * HALF;
    const float* base = part + (size_t)h * KSPL * HALF;
    float v = 0.0f;
    #pragma unroll
    for (int z = 0; z < KSPL; z++) v += base[(size_t)z * HALF + j];
    Wh[i] = v;
    int col = i & 63;
    float vs = v * a_src[col];
    float vd = v * a_dst[col];
    #pragma unroll
    for (int o = 16; o > 0; o >>= 1) {
        vs += __shfl_down_sync(FULLM, vs, o);
        vd += __shfl_down_sync(FULLM, vd, o);
    }
    __shared__ float sh[2][8];
    int wid = threadIdx.x >> 5;
    if ((threadIdx.x & 31) == 0) { sh[0][wid] = vs; sh[1][wid] = vd; }
    __syncthreads();
    if ((threadIdx.x & 63) == 0) {
        int row = i >> 6;
        s[row] = sh[0][wid] + sh[0][wid + 1];
        d[row] = sh[1][wid] + sh[1][wid + 1];
    }
}

// ---------------- warp-per-row attention (online softmax), 8192 rows ----------
__global__ void att_warp_kernel(const int* __restrict__ idx, const int* __restrict__ cnt,
                                const float* __restrict__ s, const float* __restrict__ d,
                                const float* __restrict__ Wh, float* __restrict__ out) {
    int row = blockIdx.x * 8 + (threadIdx.x >> 5);
    int lane = threadIdx.x & 31;
    if (row >= 2 * NN) return;
    int grow = row & (NN - 1);
    int off = row & NN;
    int n = cnt[grow];
    const int* lst = idx + (size_t)grow * MAXNNZ;
    float si = s[row];
    float m = -3.4e38f, ssum = 0.0f, a0 = 0.0f, a1 = 0.0f;
    for (int base = 0; base < n; base += 32) {
        int t = base + lane;
        int j = 0;
        float e = -3.4e38f;
        if (t < n) {
            j = lst[t];
            float v = si + d[j + off];
            e = v > 0.0f ? v : 0.2f * v;
        }
        float cm = e;
        #pragma unroll
        for (int o = 16; o > 0; o >>= 1) cm = fmaxf(cm, __shfl_xor_sync(FULLM, cm, o));
        float nm = fmaxf(m, cm);
        float scale = expf(m - nm);
        a0 *= scale; a1 *= scale; ssum *= scale;
        float w = (t < n) ? expf(e - nm) : 0.0f;
        float cs = w;
        #pragma unroll
        for (int o = 16; o > 0; o >>= 1) cs += __shfl_xor_sync(FULLM, cs, o);
        ssum += cs;
        int lim = min(32, n - base);
        for (int q = 0; q < lim; q++) {
            float wq = __shfl_sync(FULLM, w, q);
            int jq = __shfl_sync(FULLM, j, q);
            const float* r = Wh + (size_t)(jq + off) * 64;
            a0 += wq * r[lane];
            a1 += wq * r[lane + 32];
        }
        m = nm;
    }
    float inv = 1.0f / ssum;
    out[(size_t)row * 64 + lane] = a0 * inv;
    out[(size_t)row * 64 + lane + 32] = a1 * inv;
}

// ---------------- adjz = adj @ z (warp per row; z lives in d_out) -------------
__global__ void agg_warp_kernel(const int* __restrict__ idx, const int* __restrict__ cnt,
                                const float* __restrict__ z, float* __restrict__ out) {
    int row = blockIdx.x * 8 + (threadIdx.x >> 5);
    int lane = threadIdx.x & 31;
    if (row >= NN) return;
    int n = cnt[row];
    const int* lst = idx + (size_t)row * MAXNNZ;
    float a0 = 0.0f, a1 = 0.0f;
    for (int base = 0; base < n; base += 32) {
        int t = base + lane;
        int j = (t < n) ? lst[t] : 0;
        int lim = min(32, n - base);
        for (int q = 0; q < lim; q++) {
            int jq = __shfl_sync(FULLM, j, q);
            const float* r = z + (size_t)jq * 64;
            a0 += r[lane];
            a1 += r[lane + 32];
        }
    }
    out[(size_t)row * 64 + lane] = a0;
    out[(size_t)row * 64 + lane + 32] = a1;
}

// ---------------- warp-per-row readout: mean, L2-norm, sigmoid (8192 rows) ----
__global__ void readout_warp_kernel(const int* __restrict__ idx, const int* __restrict__ cnt,
                                    float* __restrict__ dcat) {
    int row = blockIdx.x * 8 + (threadIdx.x >> 5);
    int lane = threadIdx.x & 31;
    if (row >= 2 * NN) return;
    int grow = row & (NN - 1);
    int n = cnt[grow];
    const int* lst = idx + (size_t)grow * MAXNNZ;
    int off = (row < NN) ? 2 * NN : 3 * NN;
    float a0 = 0.0f, a1 = 0.0f;
    for (int base = 0; base < n; base += 32) {
        int t = base + lane;
        int j = (t < n) ? lst[t] : 0;
        int lim = min(32, n - base);
        for (int q = 0; q < lim; q++) {
            int jq = __shfl_sync(FULLM, j, q);
            const float* r = dcat + (size_t)(off + jq) * 64;
            a0 += r[lane];
            a1 += r[lane + 32];
        }
    }
    float invn = 1.0f / (float)n;
    float v0 = a0 * invn, v1 = a1 * invn;
    float ss = v0 * v0 + v1 * v1;
    #pragma unroll
    for (int o = 16; o > 0; o >>= 1) ss += __shfl_xor_sync(FULLM, ss, o);
    float den = fmaxf(sqrtf(ss), 1e-12f);
    float x0 = v0 / den, x1 = v1 / den;
    dcat[(size_t)row * 64 + lane] = 1.0f / (1.0f + expf(-x0));
    dcat[(size_t)row * 64 + lane + 32] = 1.0f / (1.0f + expf(-x1));
}

// ---------------- bilinear outputs (warp per logical row, 8192 rows) ----------
__global__ void bilin_warp_kernel(const float* __restrict__ qcat, const float* __restrict__ u,
                                  const float* __restrict__ b, float* __restrict__ ret,
                                  float* __restrict__ reta) {
    int row = blockIdx.x * 8 + (threadIdx.x >> 5);
    int lane = threadIdx.x & 31;
    if (row >= 2 * NN) return;
    int r = row & (NN - 1);
    const float* ur = u + (size_t)row * 64;
    const float* xpl = qcat + (size_t)(2 * NN + r) * 64;
    const float* xmi = qcat + (size_t)(3 * NN + r) * 64;
    float v0, v1;
    if (row < NN) {
        v0 = xpl[lane] * ur[lane] + xpl[lane + 32] * ur[lane + 32];
        v1 = xmi[lane] * ur[lane] + xmi[lane + 32] * ur[lane + 32];
    } else {
        v0 = xmi[lane] * ur[lane] + xmi[lane + 32] * ur[lane + 32];
        v1 = xpl[lane] * ur[lane] + xpl[lane + 32] * ur[lane + 32];
    }
    #pragma unroll
    for (int o = 16; o > 0; o >>= 1) {
        v0 += __shfl_down_sync(FULLM, v0, o);
        v1 += __shfl_down_sync(FULLM, v1, o);
    }
    if (lane == 0) {
        float* dst = (row < NN) ? ret : reta;
        dst[(size_t)r * 2 + 0] = v0 + b[0];
        dst[(size_t)r * 2 + 1] = v1 + b[0];
    }
}

// ---------------- host ----------------
static void* sym(const void* s) {
    void* p = nullptr;
    cudaGetSymbolAddress(&p, s);
    return p;
}

extern "C" void kernel_launch(void* const* d_in, const int* in_sizes, int n_in,
                              void* d_out, int out_size) {
    const float* feat   = (const float*)d_in[0];
    const float* feat_a = (const float*)d_in[1];
    const float* adj    = (const float*)d_in[2];
    const float* gn     = (const float*)d_in[3];
    const float* w1     = (const float*)d_in[4];
    const float* w2     = (const float*)d_in[5];
    const float* attW   = (const float*)d_in[6];
    const float* a_src  = (const float*)d_in[7];
    const float* a_dst  = (const float*)d_in[8];
    const float* mW1 = (const float*)d_in[9];  const float* mb1 = (const float*)d_in[10];
    const float* mW2 = (const float*)d_in[11]; const float* mb2 = (const float*)d_in[12];
    const float* mW3 = (const float*)d_in[13]; const float* mb3 = (const float*)d_in[14];
    const float* dW1 = (const float*)d_in[15]; const float* db1 = (const float*)d_in[16];
    const float* dW2 = (const float*)d_in[17]; const float* db2 = (const float*)d_in[18];
    const float* bilW = (const float*)d_in[19];
    const float* bilb = (const float*)d_in[20];

    float* out      = (float*)d_out;
    float* out_h    = out + (size_t)NN * FOUT;
    float* out_ret  = out_h + (size_t)NN * FIN;
    float* out_reta = out_ret + (size_t)NN * 2;

    float* Wh   = (float*)sym(g_Wh);
    float* sv   = (float*)sym(g_s);
    float* dv   = (float*)sym(g_d);
    float* att  = (float*)sym(g_att);
    float* t1   = (float*)sym(g_t1);
    float* t2   = (float*)sym(g_t2);
    float* adjz = (float*)sym(g_adjz);
    float* dcat = (float*)sym(g_dcat);
    float* dh   = (float*)sym(g_dh);
    float* qcat = (float*)sym(g_qcat);
    float* u    = (float*)sym(g_u);
    float* part = (float*)sym(g_part);
    float* Bhi  = (float*)sym(g_Bhi);
    float* Blo  = (float*)sym(g_Blo);
    int* aidx = (int*)sym(g_adj_idx); int* acnt = (int*)sym(g_adj_cnt);
    int* gidx = (int*)sym(g_gn_idx);  int* gcnt = (int*)sym(g_gn_cnt);

    const int M2 = 2 * NN;   // 8192
    const int M4 = 4 * NN;   // 16384
    const long long PS = (long long)NN * FOUT;

    // 1. sparse lists + fused fold(w1@attW)->hi/lo + weight split
    build_list_kernel<<<dim3(NN, 2), 256>>>(adj, aidx, acnt, gn, gidx, gcnt);
    fold_w1_kernel<<<(FIN + 3) / 4, 256>>>(w1, attW, Bhi, Blo);
    {
        SplitArgs sa;
        sa.src[0] = w2;   sa.n[0] = FOUT * FIN;  sa.off[0] = OFF_W2;  sa.tr[0] = 0;
        sa.src[1] = mW1;  sa.n[1] = 64 * 256;    sa.off[1] = OFF_MW1; sa.tr[1] = 0;
        sa.src[2] = mW2;  sa.n[2] = 256 * 128;   sa.off[2] = OFF_MW2; sa.tr[2] = 0;
        sa.src[3] = mW3;  sa.n[3] = 128 * 64;    sa.off[3] = OFF_MW3; sa.tr[3] = 0;
        sa.src[4] = dW1;  sa.n[4] = 64 * 128;    sa.off[4] = OFF_DW1; sa.tr[4] = 0;
        sa.src[5] = dW2;  sa.n[5] = 128 * 64;    sa.off[5] = OFF_DW2; sa.tr[5] = 0;
        sa.src[6] = bilW; sa.n[6] = 64 * 64;     sa.off[6] = OFF_WT;  sa.tr[6] = 1;
        split_kernel<<<dim3((FOUT * FIN + 255) / 256, 7), 256>>>(sa, Bhi, Blo);
    }

    // 2. part = [feat; feat_a] @ w1p  (3-stage cp.async tf32, split-K=6)
    gemm_cp<<<dim3(1, NN / 128, 2 * KSPL), 256>>>(
        feat, feat_a, Bhi + OFF_W1, part, NN, FOUT, FIN, 512, KSPL, PS);
    reduce_sd_kernel<<<(M2 * FOUT) / 256, 256>>>(part, a_src, a_dst, Wh, sv, dv);

    // 3. attention + MLP over 8192 rows (1xtf32; round-3 anchor: full-1x = 4.87e-4)
    att_warp_kernel<<<M2 / 8, 256>>>(aidx, acnt, sv, dv, Wh, att);
    gemm_tc3<1, 4, 16><<<dim3(4, M2 / 64, 1), 128>>>(att, Bhi + OFF_MW1, Blo + OFF_MW1,
                                                     mb1, t1, nullptr, M2, 256, 64, 1);
    gemm_tc3<1, 4, 16><<<dim3(2, M2 / 64, 1), 128>>>(t1, Bhi + OFF_MW2, Blo + OFF_MW2,
                                                     mb2, t2, nullptr, M2, 128, 256, 1);
    gemm_tc3<1, 4, 16><<<dim3(1, M2 / 64, 1), 128>>>(t2, Bhi + OFF_MW3, Blo + OFF_MW3,
                                                     mb3, out, dcat + (size_t)M2 * FOUT,
                                                     M2, 64, 128, 3);

    // 4. h = (adj @ z) @ w2  (z read from d_out; cp.async tf32)
    agg_warp_kernel<<<NN / 8, 256>>>(aidx, acnt, out, adjz);
    gemm_cp<<<dim3((FIN + 63) / 64, NN / 128, 1), 256>>>(
        adjz, nullptr, Bhi + OFF_W2, out_h, NN, FIN, FOUT, FOUT, 1, 0);

    // 5. readouts -> dcat[0..8191] = [gv; gva]
    readout_warp_kernel<<<M2 / 8, 256>>>(gidx, gcnt, dcat);

    // 6. discriminator MLP over all 16384 rows -> qcat = [dc; dca; dpl; dmi]
    gemm_tc3<1, 4, 16><<<dim3(2, M4 / 64, 1), 128>>>(dcat, Bhi + OFF_DW1, Blo + OFF_DW1,
                                                     db1, dh, nullptr, M4, 128, 64, 1);
    gemm_tc3<1, 4, 16><<<dim3(1, M4 / 64, 1), 128>>>(dh, Bhi + OFF_DW2, Blo + OFF_DW2,
                                                     db2, qcat, nullptr, M4, 64, 128, 0);

    // 7. bilinear
    gemm_tc3<1, 4, 16><<<dim3(1, M2 / 64, 1), 128>>>(qcat, Bhi + OFF_WT, Blo + OFF_WT,
                                                     nullptr, u, nullptr, M2, 64, 64, 0);
    bilin_warp_kernel<<<M2 / 8, 256>>>(qcat, u, bilb, out_ret, out_reta);
}